// round 1
// baseline (speedup 1.0000x reference)
#include <cuda_runtime.h>
#include <cuda_bf16.h>
#include <math.h>

#define NATM 200000
#define NBLK 50000
#define NE   450000
#define NG   64
#define HID  128
#define RAD  64
#define EDGEF 256
#define NLAY 3

// ---- scratch layout (single __device__ buffer, ~295 MB) ----
// h [NBLK*128] | Zb [NBLK*3] | cnt [NBLK] | A [NBLK*256] | B [NBLK*256] |
// agg [NBLK*256] | rbf [NE*64] | Wc [3*64*256] | Gacc [64*128]
static const size_t OFF_H    = 0;
static const size_t OFF_ZB   = 6400000;
static const size_t OFF_CNT  = 6550000;
static const size_t OFF_A    = 6600000;
static const size_t OFF_B    = 19400000;
static const size_t OFF_AGG  = 32200000;
static const size_t OFF_RBF  = 45000000;
static const size_t OFF_WC   = 73800000;
static const size_t OFF_GACC = 73849152;
static const size_t SCR_TOTAL = 73857344;

__device__ __align__(16) float g_scratch[SCR_TOTAL];

__device__ __forceinline__ float silu_f(float x) {
    return x / (1.0f + __expf(-x));
}

// ---------------------------------------------------------------------------
// zero (float4 grid-stride)
// ---------------------------------------------------------------------------
__global__ void k_zero4(float* __restrict__ p, int n4) {
    float4 z = make_float4(0.f, 0.f, 0.f, 0.f);
    for (int i = blockIdx.x * blockDim.x + threadIdx.x; i < n4;
         i += gridDim.x * blockDim.x) {
        ((float4*)p)[i] = z;
    }
}

// ---------------------------------------------------------------------------
// pooling: atoms -> blocks (atomic scatter). One warp per atom.
// ---------------------------------------------------------------------------
__global__ void k_pool_scatter(const float* __restrict__ H,
                               const float* __restrict__ Z,
                               const int* __restrict__ block_id,
                               float* __restrict__ hacc,
                               float* __restrict__ zacc,
                               float* __restrict__ cnt) {
    int gt = blockIdx.x * blockDim.x + threadIdx.x;
    int a = gt >> 5;
    int lane = gt & 31;
    if (a >= NATM) return;
    int b = block_id[a];
#pragma unroll
    for (int i = 0; i < 4; i++) {
        int c = lane + 32 * i;
        atomicAdd(&hacc[(size_t)b * HID + c], H[(size_t)a * HID + c]);
    }
    if (lane < 3) atomicAdd(&zacc[b * 3 + lane], Z[a * 3 + lane]);
    if (lane == 0) atomicAdd(&cnt[b], 1.0f);
}

// divide by clamped count; write Hb to output and keep in h. One warp per block.
__global__ void k_pool_div(float* __restrict__ h, float* __restrict__ zb,
                           const float* __restrict__ cnt,
                           float* __restrict__ out_Hb) {
    int gt = blockIdx.x * blockDim.x + threadIdx.x;
    int b = gt >> 5;
    int lane = gt & 31;
    if (b >= NBLK) return;
    float inv = 1.0f / fmaxf(cnt[b], 1.0f);
#pragma unroll
    for (int i = 0; i < 4; i++) {
        size_t idx = (size_t)b * HID + lane + 32 * i;
        float v = h[idx] * inv;
        h[idx] = v;
        out_Hb[idx] = v;
    }
    if (lane < 3) zb[b * 3 + lane] *= inv;
}

// ---------------------------------------------------------------------------
// rbf: one warp per edge; lane computes 2 of 64 gaussians
// ---------------------------------------------------------------------------
__global__ void k_rbf(const int* __restrict__ edges,
                      const float* __restrict__ zb,
                      float* __restrict__ rbf) {
    int gt = blockIdx.x * blockDim.x + threadIdx.x;
    int e = gt >> 5;
    int lane = gt & 31;
    if (e >= NE) return;
    int s = edges[e];
    int t = edges[NE + e];
    float dx = zb[s * 3 + 0] - zb[t * 3 + 0];
    float dy = zb[s * 3 + 1] - zb[t * 3 + 1];
    float dz = zb[s * 3 + 2] - zb[t * 3 + 2];
    float d = sqrtf(dx * dx + dy * dy + dz * dz + 1e-12f);
    const float step = 6.0f / 63.0f;
#pragma unroll
    for (int i = 0; i < 2; i++) {
        int k = lane + 32 * i;
        float diff = d - step * (float)k;
        rbf[(size_t)e * RAD + k] = __expf(-10.0f * diff * diff);
    }
}

// ---------------------------------------------------------------------------
// SGEMM: C[M,N] = A[M,K] @ B[K,N].  64x64 tile, BK=16, 256 threads, 4x4/thread.
// epi==1: C = C + silu(acc)   (in-place h update)
// Requires: K % 16 == 0, N % 64 == 0. M guarded.
// ---------------------------------------------------------------------------
__global__ void k_sgemm(const float* __restrict__ A,
                        const float* __restrict__ B,
                        float* __restrict__ C,
                        int M, int N, int K, int epi) {
    __shared__ float As[16][64];
    __shared__ float Bs[16][64];
    int tid = threadIdx.x;
    int tx = tid & 15;       // col group
    int ty = tid >> 4;       // row group
    int rowBase = blockIdx.y * 64;
    int colBase = blockIdx.x * 64;

    // A tile loader: row = tid/4, cols = (tid%4)*4 .. +3
    int ar = tid >> 2;
    int ac = (tid & 3) * 4;
    // B tile loader: row = tid/16, cols = (tid%16)*4
    int br = tid >> 4;
    int bc = (tid & 15) * 4;

    float acc[4][4];
#pragma unroll
    for (int i = 0; i < 4; i++)
#pragma unroll
        for (int j = 0; j < 4; j++) acc[i][j] = 0.f;

    for (int k0 = 0; k0 < K; k0 += 16) {
        float4 av = make_float4(0.f, 0.f, 0.f, 0.f);
        int gr = rowBase + ar;
        if (gr < M) av = *(const float4*)&A[(size_t)gr * K + k0 + ac];
        As[ac + 0][ar] = av.x;
        As[ac + 1][ar] = av.y;
        As[ac + 2][ar] = av.z;
        As[ac + 3][ar] = av.w;
        float4 bv = *(const float4*)&B[(size_t)(k0 + br) * N + colBase + bc];
        *(float4*)&Bs[br][bc] = bv;
        __syncthreads();
#pragma unroll
        for (int k = 0; k < 16; k++) {
            float4 a4 = *(const float4*)&As[k][ty * 4];
            float4 b4 = *(const float4*)&Bs[k][tx * 4];
            float aa[4] = {a4.x, a4.y, a4.z, a4.w};
            float bb[4] = {b4.x, b4.y, b4.z, b4.w};
#pragma unroll
            for (int i = 0; i < 4; i++)
#pragma unroll
                for (int j = 0; j < 4; j++) acc[i][j] += aa[i] * bb[j];
        }
        __syncthreads();
    }

#pragma unroll
    for (int i = 0; i < 4; i++) {
        int r = rowBase + ty * 4 + i;
        if (r >= M) continue;
#pragma unroll
        for (int j = 0; j < 4; j++) {
            int c = colBase + tx * 4 + j;
            float v = acc[i][j];
            size_t idx = (size_t)r * N + c;
            if (epi == 1) v = C[idx] + silu_f(v);
            C[idx] = v;
        }
    }
}

// ---------------------------------------------------------------------------
// edge message: m = silu(A[src] + B[dst] + rbf @ Wc[l]); agg[dst] += m
// 256 threads = one message column each; Wc column held in 64 registers.
// EPG=8 edges per smem stage; persistent grid.
// ---------------------------------------------------------------------------
#define EPG 8
__global__ void __launch_bounds__(256)
k_edge(const int* __restrict__ edges,
       const float* __restrict__ Wcl,     // [64,256] for this layer
       const float* __restrict__ Ag,      // [NBLK,256]
       const float* __restrict__ Bg,      // [NBLK,256]
       const float* __restrict__ rbf,     // [NE,64]
       float* __restrict__ agg) {         // [NBLK,256]
    int j = threadIdx.x;
    float w[64];
#pragma unroll
    for (int k = 0; k < 64; k++) w[k] = Wcl[k * 256 + j];

    __shared__ float rbf_s[EPG * 64];
    __shared__ int ss[EPG], ds[EPG];

    const int nGroups = NE / EPG;  // 56250, exact
    for (int g = blockIdx.x; g < nGroups; g += gridDim.x) {
        int base = g * EPG;
        if (j < (EPG * 64 / 4)) {
            *(float4*)&rbf_s[j * 4] =
                *(const float4*)&rbf[(size_t)base * 64 + j * 4];
        }
        if (j < EPG) {
            ss[j] = edges[base + j];
            ds[j] = edges[NE + base + j];
        }
        __syncthreads();

        // prefetch gathers for all EPG edges (MLP)
        float accv[EPG];
        int dloc[EPG];
#pragma unroll
        for (int i = 0; i < EPG; i++) {
            int s = ss[i];
            int d = ds[i];
            dloc[i] = d;
            accv[i] = Ag[(size_t)s * 256 + j] + Bg[(size_t)d * 256 + j];
        }
#pragma unroll 1
        for (int i = 0; i < EPG; i++) {
            const float* r = &rbf_s[i * 64];
            float acc = accv[i];
#pragma unroll
            for (int k = 0; k < 64; k++) acc += r[k] * w[k];
            float v = silu_f(acc);
            atomicAdd(&agg[(size_t)dloc[i] * 256 + j], v);
        }
        __syncthreads();
    }
}

// ---------------------------------------------------------------------------
// row l2norm of tmp[NBLK,128] -> out; also scatter into graph accumulator
// ---------------------------------------------------------------------------
__global__ void k_rownorm_scatter(const float* __restrict__ tmp,
                                  const int* __restrict__ batch_id,
                                  float* __restrict__ out_block,
                                  float* __restrict__ gacc) {
    int gt = blockIdx.x * blockDim.x + threadIdx.x;
    int r = gt >> 5;
    int lane = gt & 31;
    if (r >= NBLK) return;
    float v[4];
    float ss = 0.f;
#pragma unroll
    for (int i = 0; i < 4; i++) {
        v[i] = tmp[(size_t)r * HID + lane + 32 * i];
        ss += v[i] * v[i];
    }
#pragma unroll
    for (int o = 16; o > 0; o >>= 1) ss += __shfl_xor_sync(0xffffffffu, ss, o);
    float inv = 1.0f / fmaxf(sqrtf(ss), 1e-12f);
    int g = batch_id[r];
#pragma unroll
    for (int i = 0; i < 4; i++) {
        int c = lane + 32 * i;
        float nv = v[i] * inv;
        out_block[(size_t)r * HID + c] = nv;
        atomicAdd(&gacc[g * HID + c], nv);
    }
}

__global__ void k_graphnorm(const float* __restrict__ gacc,
                            float* __restrict__ out_graph) {
    int gt = blockIdx.x * blockDim.x + threadIdx.x;
    int r = gt >> 5;
    int lane = gt & 31;
    if (r >= NG) return;
    float v[4];
    float ss = 0.f;
#pragma unroll
    for (int i = 0; i < 4; i++) {
        v[i] = gacc[r * HID + lane + 32 * i];
        ss += v[i] * v[i];
    }
#pragma unroll
    for (int o = 16; o > 0; o >>= 1) ss += __shfl_xor_sync(0xffffffffu, ss, o);
    float inv = 1.0f / fmaxf(sqrtf(ss), 1e-12f);
#pragma unroll
    for (int i = 0; i < 4; i++)
        out_graph[r * HID + lane + 32 * i] = v[i] * inv;
}

// ---------------------------------------------------------------------------
// launch
// ---------------------------------------------------------------------------
extern "C" void kernel_launch(void* const* d_in, const int* in_sizes, int n_in,
                              void* d_out, int out_size) {
    const float* H      = (const float*)d_in[0];
    const float* Z      = (const float*)d_in[1];
    const float* W_rbf  = (const float*)d_in[2];
    const float* Wm1    = (const float*)d_in[3];
    const float* Wm2    = (const float*)d_in[4];
    const float* We     = (const float*)d_in[5];
    const float* Wupd   = (const float*)d_in[6];
    const float* W_out  = (const float*)d_in[7];
    const int*   block_id = (const int*)d_in[8];
    const int*   batch_id = (const int*)d_in[9];
    const int*   edges    = (const int*)d_in[10];

    float* out = (float*)d_out;
    float* out_Hb    = out;                    // [NBLK,128]
    float* out_block = out + (size_t)NBLK * HID;       // [NBLK,128]
    float* out_graph = out + 2 * (size_t)NBLK * HID;   // [NG,128]

    void* scrv = nullptr;
    cudaGetSymbolAddress(&scrv, g_scratch);
    float* scr  = (float*)scrv;
    float* s_h    = scr + OFF_H;
    float* s_zb   = scr + OFF_ZB;
    float* s_cnt  = scr + OFF_CNT;
    float* s_A    = scr + OFF_A;
    float* s_B    = scr + OFF_B;
    float* s_agg  = scr + OFF_AGG;
    float* s_rbf  = scr + OFF_RBF;
    float* s_Wc   = scr + OFF_WC;
    float* s_gacc = scr + OFF_GACC;

    // zero pooling accumulators (h|Zb|cnt contiguous = 6,600,000 floats) + Gacc
    k_zero4<<<4096, 256>>>(s_h, 6600000 / 4);
    k_zero4<<<8, 256>>>(s_gacc, (NG * HID) / 4);

    // pooling
    k_pool_scatter<<<(NATM * 32 + 255) / 256, 256>>>(H, Z, block_id, s_h, s_zb, s_cnt);
    k_pool_div<<<(NBLK * 32 + 255) / 256, 256>>>(s_h, s_zb, s_cnt, out_Hb);

    // rbf features
    k_rbf<<<(NE * 32 + 255) / 256, 256>>>(edges, s_zb, s_rbf);

    // Wc[l] = W_rbf @ We[l]   (64x256 @ 256x256)
    for (int l = 0; l < NLAY; l++) {
        dim3 grid(256 / 64, (64 + 63) / 64);
        k_sgemm<<<grid, 256>>>(W_rbf, We + (size_t)l * 256 * 256,
                               s_Wc + (size_t)l * 64 * 256, 64, 256, 256, 0);
    }

    dim3 gridNB256(256 / 64, (NBLK + 63) / 64);
    dim3 gridNB128(128 / 64, (NBLK + 63) / 64);

    for (int l = 0; l < NLAY; l++) {
        // A = h@Wm1[l], B = h@Wm2[l]
        k_sgemm<<<gridNB256, 256>>>(s_h, Wm1 + (size_t)l * HID * EDGEF, s_A,
                                    NBLK, EDGEF, HID, 0);
        k_sgemm<<<gridNB256, 256>>>(s_h, Wm2 + (size_t)l * HID * EDGEF, s_B,
                                    NBLK, EDGEF, HID, 0);
        // agg = 0
        k_zero4<<<8192, 256>>>(s_agg, (NBLK * EDGEF) / 4);
        // edge messages + scatter
        k_edge<<<4096, 256>>>(edges, s_Wc + (size_t)l * 64 * 256, s_A, s_B,
                              s_rbf, s_agg);
        // h = h + silu(agg @ Wupd[l])
        k_sgemm<<<gridNB128, 256>>>(s_agg, Wupd + (size_t)l * EDGEF * HID, s_h,
                                    NBLK, HID, EDGEF, 1);
    }

    // block_repr = l2norm(h @ W_out)  (tmp in s_A)
    k_sgemm<<<gridNB128, 256>>>(s_h, W_out, s_A, NBLK, HID, HID, 0);
    k_rownorm_scatter<<<(NBLK * 32 + 255) / 256, 256>>>(s_A, batch_id,
                                                        out_block, s_gacc);
    k_graphnorm<<<(NG * 32 + 255) / 256, 256>>>(s_gacc, out_graph);
}

// round 2
// speedup vs baseline: 1.7442x; 1.7442x over previous
#include <cuda_runtime.h>
#include <cuda_bf16.h>
#include <math.h>

#define NATM 200000
#define NBLK 50000
#define NE   450000
#define NG   64
#define HID  128
#define RAD  64
#define EDGEF 256
#define NLAY 3

// ---- scratch layout (single __device__ buffer) ----
// h [NBLK*128] | zc [NBLK*4] (z0,z1,z2,cnt) | A [NBLK*256] | B [NBLK*256] |
// agg [NBLK*256] | rbf [NE*64] | Wc [3*64*256] | Gacc [64*128]
static const size_t OFF_H    = 0;
static const size_t OFF_ZC   = 6400000;
static const size_t OFF_A    = 6600000;
static const size_t OFF_B    = 19400000;
static const size_t OFF_AGG  = 32200000;
static const size_t OFF_RBF  = 45000000;
static const size_t OFF_WC   = 73800000;
static const size_t OFF_GACC = 73849152;
static const size_t SCR_TOTAL = 73857344;

__device__ __align__(16) float g_scratch[SCR_TOTAL];

__device__ __forceinline__ float silu_f(float x) {
    return x / (1.0f + __expf(-x));
}

__device__ __forceinline__ unsigned cvt_tf32(float f) {
    unsigned u;
    asm("cvt.rna.tf32.f32 %0, %1;" : "=r"(u) : "f"(f));
    return u;
}

__device__ __forceinline__ void mma_tf32(float* c, const unsigned* a,
                                         const unsigned* b) {
    asm volatile(
        "mma.sync.aligned.m16n8k8.row.col.f32.tf32.tf32.f32 "
        "{%0,%1,%2,%3}, {%4,%5,%6,%7}, {%8,%9}, {%0,%1,%2,%3};"
        : "+f"(c[0]), "+f"(c[1]), "+f"(c[2]), "+f"(c[3])
        : "r"(a[0]), "r"(a[1]), "r"(a[2]), "r"(a[3]), "r"(b[0]), "r"(b[1]));
}

__device__ __forceinline__ void red4(float* p, float4 v) {
    asm volatile("red.global.add.v4.f32 [%0], {%1,%2,%3,%4};"
                 :: "l"(p), "f"(v.x), "f"(v.y), "f"(v.z), "f"(v.w)
                 : "memory");
}

// ---------------------------------------------------------------------------
// zero (float4 grid-stride)
// ---------------------------------------------------------------------------
__global__ void k_zero4(float* __restrict__ p, int n4) {
    float4 z = make_float4(0.f, 0.f, 0.f, 0.f);
    for (int i = blockIdx.x * blockDim.x + threadIdx.x; i < n4;
         i += gridDim.x * blockDim.x) {
        ((float4*)p)[i] = z;
    }
}

// ---------------------------------------------------------------------------
// pooling: atoms -> blocks via red.v4. One warp per atom.
// ---------------------------------------------------------------------------
__global__ void k_pool_scatter(const float* __restrict__ H,
                               const float* __restrict__ Z,
                               const int* __restrict__ block_id,
                               float* __restrict__ hacc,
                               float* __restrict__ zc) {
    int gt = blockIdx.x * blockDim.x + threadIdx.x;
    int a = gt >> 5;
    int lane = gt & 31;
    if (a >= NATM) return;
    int b = block_id[a];
    float4 v = *(const float4*)&H[(size_t)a * HID + lane * 4];
    red4(&hacc[(size_t)b * HID + lane * 4], v);
    if (lane == 0) {
        float4 z = make_float4(Z[a * 3 + 0], Z[a * 3 + 1], Z[a * 3 + 2], 1.0f);
        red4(&zc[b * 4], z);
    }
}

// divide by clamped count; write Hb to output and keep in h. One warp per block.
__global__ void k_pool_div(float* __restrict__ h, float* __restrict__ zc,
                           float* __restrict__ out_Hb) {
    int gt = blockIdx.x * blockDim.x + threadIdx.x;
    int b = gt >> 5;
    int lane = gt & 31;
    if (b >= NBLK) return;
    float inv = 1.0f / fmaxf(zc[b * 4 + 3], 1.0f);
    float4 v = *(float4*)&h[(size_t)b * HID + lane * 4];
    v.x *= inv; v.y *= inv; v.z *= inv; v.w *= inv;
    *(float4*)&h[(size_t)b * HID + lane * 4] = v;
    *(float4*)&out_Hb[(size_t)b * HID + lane * 4] = v;
    if (lane < 3) zc[b * 4 + lane] *= inv;
}

// ---------------------------------------------------------------------------
// rbf: one warp per edge; stores tf32-rounded bit patterns
// ---------------------------------------------------------------------------
__global__ void k_rbf(const int* __restrict__ edges,
                      const float* __restrict__ zc,
                      float* __restrict__ rbf) {
    int gt = blockIdx.x * blockDim.x + threadIdx.x;
    int e = gt >> 5;
    int lane = gt & 31;
    if (e >= NE) return;
    int s = edges[e];
    int t = edges[NE + e];
    float dx = zc[s * 4 + 0] - zc[t * 4 + 0];
    float dy = zc[s * 4 + 1] - zc[t * 4 + 1];
    float dz = zc[s * 4 + 2] - zc[t * 4 + 2];
    float d = sqrtf(dx * dx + dy * dy + dz * dz + 1e-12f);
    const float step = 6.0f / 63.0f;
#pragma unroll
    for (int i = 0; i < 2; i++) {
        int k = lane + 32 * i;
        float diff = d - step * (float)k;
        float v = __expf(-10.0f * diff * diff);
        rbf[(size_t)e * RAD + k] = __uint_as_float(cvt_tf32(v));
    }
}

// ---------------------------------------------------------------------------
// tf32 tensor GEMM: C[M,N] = A[M,K] @ B[K,N]
// BM=128 BN=64 BK=32, 256 threads, warps 4x2, warp tile 32x32.
// epi==1: C = C + silu(acc). Requires K%32==0, N%64==0.
// ---------------------------------------------------------------------------
__global__ void __launch_bounds__(256)
k_gemm(const float* __restrict__ A, const float* __restrict__ B,
       float* __restrict__ C, int M, int N, int K, int epi) {
    __shared__ unsigned As[128 * 36];
    __shared__ unsigned Bs[32 * 68];
    int tid = threadIdx.x;
    int warp = tid >> 5, lane = tid & 31;
    int gid = lane >> 2, tig = lane & 3;
    int wm = (warp & 3) * 32, wn = (warp >> 2) * 32;
    int rowBase = blockIdx.y * 128, colBase = blockIdx.x * 64;

    float acc[2][4][4];
#pragma unroll
    for (int mt = 0; mt < 2; mt++)
#pragma unroll
        for (int nn = 0; nn < 4; nn++)
#pragma unroll
            for (int q = 0; q < 4; q++) acc[mt][nn][q] = 0.f;

    for (int k0 = 0; k0 < K; k0 += 32) {
        // stage A tile [128 x 32] (tf32-converted)
#pragma unroll
        for (int i = 0; i < 4; i++) {
            int r = (tid >> 3) + i * 32;
            int c4 = (tid & 7) * 4;
            float4 v = make_float4(0.f, 0.f, 0.f, 0.f);
            if (rowBase + r < M)
                v = *(const float4*)&A[(size_t)(rowBase + r) * K + k0 + c4];
            uint4 u;
            u.x = cvt_tf32(v.x); u.y = cvt_tf32(v.y);
            u.z = cvt_tf32(v.z); u.w = cvt_tf32(v.w);
            *(uint4*)&As[r * 36 + c4] = u;
        }
        // stage B tile [32 x 64]
#pragma unroll
        for (int i = 0; i < 2; i++) {
            int k = (tid >> 4) + i * 16;
            int c4 = (tid & 15) * 4;
            float4 v = *(const float4*)&B[(size_t)(k0 + k) * N + colBase + c4];
            uint4 u;
            u.x = cvt_tf32(v.x); u.y = cvt_tf32(v.y);
            u.z = cvt_tf32(v.z); u.w = cvt_tf32(v.w);
            *(uint4*)&Bs[k * 68 + c4] = u;
        }
        __syncthreads();
#pragma unroll
        for (int kk = 0; kk < 4; kk++) {
            unsigned a[2][4], b[4][2];
#pragma unroll
            for (int mt = 0; mt < 2; mt++) {
                int r = wm + mt * 16 + gid;
                a[mt][0] = As[r * 36 + kk * 8 + tig];
                a[mt][1] = As[(r + 8) * 36 + kk * 8 + tig];
                a[mt][2] = As[r * 36 + kk * 8 + tig + 4];
                a[mt][3] = As[(r + 8) * 36 + kk * 8 + tig + 4];
            }
#pragma unroll
            for (int nn = 0; nn < 4; nn++) {
                b[nn][0] = Bs[(kk * 8 + tig) * 68 + wn + nn * 8 + gid];
                b[nn][1] = Bs[(kk * 8 + tig + 4) * 68 + wn + nn * 8 + gid];
            }
#pragma unroll
            for (int mt = 0; mt < 2; mt++)
#pragma unroll
                for (int nn = 0; nn < 4; nn++)
                    mma_tf32(acc[mt][nn], a[mt], b[nn]);
        }
        __syncthreads();
    }

    // epilogue
#pragma unroll
    for (int mt = 0; mt < 2; mt++) {
#pragma unroll
        for (int nn = 0; nn < 4; nn++) {
            int r0 = rowBase + wm + mt * 16 + gid;
            int r1 = r0 + 8;
            int c = colBase + wn + nn * 8 + 2 * tig;
            if (r0 < M) {
                size_t idx = (size_t)r0 * N + c;
                if (epi == 1) {
                    C[idx]     += silu_f(acc[mt][nn][0]);
                    C[idx + 1] += silu_f(acc[mt][nn][1]);
                } else {
                    C[idx]     = acc[mt][nn][0];
                    C[idx + 1] = acc[mt][nn][1];
                }
            }
            if (r1 < M) {
                size_t idx = (size_t)r1 * N + c;
                if (epi == 1) {
                    C[idx]     += silu_f(acc[mt][nn][2]);
                    C[idx + 1] += silu_f(acc[mt][nn][3]);
                } else {
                    C[idx]     = acc[mt][nn][2];
                    C[idx + 1] = acc[mt][nn][3];
                }
            }
        }
    }
}

// ---------------------------------------------------------------------------
// edge message kernel (tensor-core): groups of 32 edges.
// m = silu(A[src] + B[dst] + rbf@Wc); agg[dst] += m (red.v4, coalesced)
// 256 threads = 8 warps; warp w owns cols [32w, 32w+32); Wc frags in regs.
// ---------------------------------------------------------------------------
__global__ void __launch_bounds__(256)
k_edge_tc(const int* __restrict__ edges,
          const float* __restrict__ Wcl,    // [64,256] for this layer
          const float* __restrict__ Ag,     // [NBLK,256]
          const float* __restrict__ Bg,     // [NBLK,256]
          const float* __restrict__ rbf,    // [NE,64], tf32 bits
          float* __restrict__ agg) {        // [NBLK,256]
    int tid = threadIdx.x;
    int warp = tid >> 5, lane = tid & 31;
    int gid = lane >> 2, tig = lane & 3;
    int nb = warp * 32;

    // Wc B-fragments: [kstep 8][ntile 4][2]
    unsigned bfr[8][4][2];
#pragma unroll
    for (int kk = 0; kk < 8; kk++)
#pragma unroll
        for (int nn = 0; nn < 4; nn++) {
            bfr[kk][nn][0] =
                cvt_tf32(Wcl[(kk * 8 + tig) * 256 + nb + nn * 8 + gid]);
            bfr[kk][nn][1] =
                cvt_tf32(Wcl[(kk * 8 + tig + 4) * 256 + nb + nn * 8 + gid]);
        }

    __shared__ unsigned rbs[32 * 68];
    __shared__ float Gs[32 * 260];
    __shared__ int ss[32], ds[32];

    const int nG = (NE + 31) / 32;
    for (int g = blockIdx.x; g < nG; g += gridDim.x) {
        int base = g * 32;
        // stage edge indices + rbf tile
        if (tid < 32) {
            int e = base + tid;
            ss[tid] = (e < NE) ? edges[e] : 0;
            ds[tid] = (e < NE) ? edges[NE + e] : 0;
        }
#pragma unroll
        for (int i = 0; i < 2; i++) {
            int idx = tid + i * 256;
            int r = idx >> 4;
            int c4 = (idx & 15) * 4;
            int e = base + r;
            float4 v = make_float4(0.f, 0.f, 0.f, 0.f);
            if (e < NE) v = *(const float4*)&rbf[(size_t)e * 64 + c4];
            uint4 u = *(uint4*)&v;
            *(uint4*)&rbs[r * 68 + c4] = u;
        }
        __syncthreads();
        // stage G = Ag[src] + Bg[dst]
#pragma unroll
        for (int i = 0; i < 8; i++) {
            int idx = tid + i * 256;
            int r = idx >> 6;
            int c4 = (idx & 63) * 4;
            int s = ss[r], d = ds[r];
            float4 a = *(const float4*)&Ag[(size_t)s * 256 + c4];
            float4 b = *(const float4*)&Bg[(size_t)d * 256 + c4];
            float4 t;
            t.x = a.x + b.x; t.y = a.y + b.y;
            t.z = a.z + b.z; t.w = a.w + b.w;
            *(float4*)&Gs[r * 260 + c4] = t;
        }
        __syncthreads();

        // mma: [32 edges x 64 rad] @ [64 x 32 cols-per-warp]
        float acc[2][4][4];
#pragma unroll
        for (int mt = 0; mt < 2; mt++)
#pragma unroll
            for (int nn = 0; nn < 4; nn++)
#pragma unroll
                for (int q = 0; q < 4; q++) acc[mt][nn][q] = 0.f;

#pragma unroll
        for (int kk = 0; kk < 8; kk++) {
            unsigned a[2][4];
#pragma unroll
            for (int mt = 0; mt < 2; mt++) {
                int r = mt * 16 + gid;
                a[mt][0] = rbs[r * 68 + kk * 8 + tig];
                a[mt][1] = rbs[(r + 8) * 68 + kk * 8 + tig];
                a[mt][2] = rbs[r * 68 + kk * 8 + tig + 4];
                a[mt][3] = rbs[(r + 8) * 68 + kk * 8 + tig + 4];
            }
#pragma unroll
            for (int mt = 0; mt < 2; mt++)
#pragma unroll
                for (int nn = 0; nn < 4; nn++)
                    mma_tf32(acc[mt][nn], a[mt], bfr[kk][nn]);
        }

        // in-place: Gs = silu(acc + Gs)
#pragma unroll
        for (int mt = 0; mt < 2; mt++) {
#pragma unroll
            for (int nn = 0; nn < 4; nn++) {
                int r0 = mt * 16 + gid;
                int r1 = r0 + 8;
                int c = nb + nn * 8 + 2 * tig;
                Gs[r0 * 260 + c]     = silu_f(acc[mt][nn][0] + Gs[r0 * 260 + c]);
                Gs[r0 * 260 + c + 1] = silu_f(acc[mt][nn][1] + Gs[r0 * 260 + c + 1]);
                Gs[r1 * 260 + c]     = silu_f(acc[mt][nn][2] + Gs[r1 * 260 + c]);
                Gs[r1 * 260 + c + 1] = silu_f(acc[mt][nn][3] + Gs[r1 * 260 + c + 1]);
            }
        }
        __syncthreads();

        // coalesced vector scatter
#pragma unroll
        for (int i = 0; i < 8; i++) {
            int idx = tid + i * 256;
            int r = idx >> 6;
            int c4 = (idx & 63) * 4;
            int e = base + r;
            if (e < NE) {
                float4 v = *(float4*)&Gs[r * 260 + c4];
                red4(&agg[(size_t)ds[r] * 256 + c4], v);
            }
        }
        __syncthreads();
    }
}

// ---------------------------------------------------------------------------
// row l2norm of tmp[NBLK,128] -> out; also scatter into graph accumulator
// ---------------------------------------------------------------------------
__global__ void k_rownorm_scatter(const float* __restrict__ tmp,
                                  const int* __restrict__ batch_id,
                                  float* __restrict__ out_block,
                                  float* __restrict__ gacc) {
    int gt = blockIdx.x * blockDim.x + threadIdx.x;
    int r = gt >> 5;
    int lane = gt & 31;
    if (r >= NBLK) return;
    float4 v = *(const float4*)&tmp[(size_t)r * HID + lane * 4];
    float ss = v.x * v.x + v.y * v.y + v.z * v.z + v.w * v.w;
#pragma unroll
    for (int o = 16; o > 0; o >>= 1) ss += __shfl_xor_sync(0xffffffffu, ss, o);
    float inv = 1.0f / fmaxf(sqrtf(ss), 1e-12f);
    int g = batch_id[r];
    float4 nv = make_float4(v.x * inv, v.y * inv, v.z * inv, v.w * inv);
    *(float4*)&out_block[(size_t)r * HID + lane * 4] = nv;
    red4(&gacc[g * HID + lane * 4], nv);
}

__global__ void k_graphnorm(const float* __restrict__ gacc,
                            float* __restrict__ out_graph) {
    int gt = blockIdx.x * blockDim.x + threadIdx.x;
    int r = gt >> 5;
    int lane = gt & 31;
    if (r >= NG) return;
    float4 v = *(const float4*)&gacc[r * HID + lane * 4];
    float ss = v.x * v.x + v.y * v.y + v.z * v.z + v.w * v.w;
#pragma unroll
    for (int o = 16; o > 0; o >>= 1) ss += __shfl_xor_sync(0xffffffffu, ss, o);
    float inv = 1.0f / fmaxf(sqrtf(ss), 1e-12f);
    float4 nv = make_float4(v.x * inv, v.y * inv, v.z * inv, v.w * inv);
    *(float4*)&out_graph[r * HID + lane * 4] = nv;
}

// ---------------------------------------------------------------------------
// launch
// ---------------------------------------------------------------------------
extern "C" void kernel_launch(void* const* d_in, const int* in_sizes, int n_in,
                              void* d_out, int out_size) {
    const float* H      = (const float*)d_in[0];
    const float* Z      = (const float*)d_in[1];
    const float* W_rbf  = (const float*)d_in[2];
    const float* Wm1    = (const float*)d_in[3];
    const float* Wm2    = (const float*)d_in[4];
    const float* We     = (const float*)d_in[5];
    const float* Wupd   = (const float*)d_in[6];
    const float* W_out  = (const float*)d_in[7];
    const int*   block_id = (const int*)d_in[8];
    const int*   batch_id = (const int*)d_in[9];
    const int*   edges    = (const int*)d_in[10];

    float* out = (float*)d_out;
    float* out_Hb    = out;                            // [NBLK,128]
    float* out_block = out + (size_t)NBLK * HID;       // [NBLK,128]
    float* out_graph = out + 2 * (size_t)NBLK * HID;   // [NG,128]

    void* scrv = nullptr;
    cudaGetSymbolAddress(&scrv, g_scratch);
    float* scr  = (float*)scrv;
    float* s_h    = scr + OFF_H;
    float* s_zc   = scr + OFF_ZC;
    float* s_A    = scr + OFF_A;
    float* s_B    = scr + OFF_B;
    float* s_agg  = scr + OFF_AGG;
    float* s_rbf  = scr + OFF_RBF;
    float* s_Wc   = scr + OFF_WC;
    float* s_gacc = scr + OFF_GACC;

    // zero pooling accumulators (h|zc contiguous = 6,600,000 floats) + Gacc
    k_zero4<<<4096, 256>>>(s_h, 6600000 / 4);
    k_zero4<<<8, 256>>>(s_gacc, (NG * HID) / 4);

    // pooling
    k_pool_scatter<<<(NATM * 32 + 255) / 256, 256>>>(H, Z, block_id, s_h, s_zc);
    k_pool_div<<<(NBLK * 32 + 255) / 256, 256>>>(s_h, s_zc, out_Hb);

    // rbf features (tf32-rounded)
    k_rbf<<<(NE * 32 + 255) / 256, 256>>>(edges, s_zc, s_rbf);

    // Wc[l] = W_rbf @ We[l]   (64x256 @ 256x256)
    for (int l = 0; l < NLAY; l++) {
        dim3 grid(256 / 64, 1);
        k_gemm<<<grid, 256>>>(W_rbf, We + (size_t)l * 256 * 256,
                              s_Wc + (size_t)l * 64 * 256, 64, 256, 256, 0);
    }

    dim3 gridNB256(256 / 64, (NBLK + 127) / 128);
    dim3 gridNB128(128 / 64, (NBLK + 127) / 128);

    for (int l = 0; l < NLAY; l++) {
        // A = h@Wm1[l], B = h@Wm2[l]
        k_gemm<<<gridNB256, 256>>>(s_h, Wm1 + (size_t)l * HID * EDGEF, s_A,
                                   NBLK, EDGEF, HID, 0);
        k_gemm<<<gridNB256, 256>>>(s_h, Wm2 + (size_t)l * HID * EDGEF, s_B,
                                   NBLK, EDGEF, HID, 0);
        // agg = 0
        k_zero4<<<8192, 256>>>(s_agg, (NBLK * EDGEF) / 4);
        // edge messages + scatter
        k_edge_tc<<<2048, 256>>>(edges, s_Wc + (size_t)l * 64 * 256, s_A, s_B,
                                 s_rbf, s_agg);
        // h = h + silu(agg @ Wupd[l])
        k_gemm<<<gridNB128, 256>>>(s_agg, Wupd + (size_t)l * EDGEF * HID, s_h,
                                   NBLK, HID, EDGEF, 1);
    }

    // block_repr = l2norm(h @ W_out)  (tmp in s_A)
    k_gemm<<<gridNB128, 256>>>(s_h, W_out, s_A, NBLK, HID, HID, 0);
    k_rownorm_scatter<<<(NBLK * 32 + 255) / 256, 256>>>(s_A, batch_id,
                                                        out_block, s_gacc);
    k_graphnorm<<<(NG * 32 + 255) / 256, 256>>>(s_gacc, out_graph);
}

// round 3
// speedup vs baseline: 2.0516x; 1.1762x over previous
#include <cuda_runtime.h>
#include <cuda_bf16.h>
#include <math.h>

#define NATM 200000
#define NBLK 50000
#define NE   450000
#define NG   64
#define HID  128
#define RAD  64
#define EDGEF 256
#define NLAY 3

// ---- scratch layout (single __device__ buffer, floats) ----
static const size_t OFF_H     = 0;          // [NBLK*128]
static const size_t OFF_ZC    = 6400000;    // [NBLK*4] z0,z1,z2,cnt
static const size_t OFF_A     = 6600000;    // [NBLK*256]
static const size_t OFF_B     = 19400000;   // [NBLK*256]
static const size_t OFF_AGG   = 32200000;   // [NBLK*256]
static const size_t OFF_RBF   = 45000000;   // [NE*64]
static const size_t OFF_WC    = 73800000;   // [3*64*256]
static const size_t OFF_GACC  = 73849152;   // [64*128]
static const size_t OFF_START = 73857344;   // int[NBLK+1] (50016)
static const size_t OFF_CNT   = 73907360;   // int[NBLK]   (50016)
static const size_t OFF_TOPS  = 73957376;   // int[128]
static const size_t OFF_SSRC  = 73957504;   // int[NE]     (450016)
static const size_t OFF_SDST  = 74407520;   // int[NE]     (450016)
static const size_t SCR_TOTAL = 74857536;

__device__ __align__(16) float g_scratch[SCR_TOTAL];

#define NTOPS 98   // ceil(NBLK/512)

__device__ __forceinline__ float silu_f(float x) {
    return x / (1.0f + __expf(-x));
}

__device__ __forceinline__ unsigned cvt_tf32(float f) {
    unsigned u;
    asm("cvt.rna.tf32.f32 %0, %1;" : "=r"(u) : "f"(f));
    return u;
}

__device__ __forceinline__ void mma_tf32(float* c, const unsigned* a,
                                         const unsigned* b) {
    asm volatile(
        "mma.sync.aligned.m16n8k8.row.col.f32.tf32.tf32.f32 "
        "{%0,%1,%2,%3}, {%4,%5,%6,%7}, {%8,%9}, {%0,%1,%2,%3};"
        : "+f"(c[0]), "+f"(c[1]), "+f"(c[2]), "+f"(c[3])
        : "r"(a[0]), "r"(a[1]), "r"(a[2]), "r"(a[3]), "r"(b[0]), "r"(b[1]));
}

__device__ __forceinline__ void red4(float* p, float4 v) {
    asm volatile("red.global.add.v4.f32 [%0], {%1,%2,%3,%4};"
                 :: "l"(p), "f"(v.x), "f"(v.y), "f"(v.z), "f"(v.w)
                 : "memory");
}

// ---------------------------------------------------------------------------
__global__ void k_zero4(float* __restrict__ p, int n4) {
    float4 z = make_float4(0.f, 0.f, 0.f, 0.f);
    for (int i = blockIdx.x * blockDim.x + threadIdx.x; i < n4;
         i += gridDim.x * blockDim.x) {
        ((float4*)p)[i] = z;
    }
}

// ---------------------------------------------------------------------------
// segment boundaries of sorted block_id: start[b] = first atom with bid >= b
// ---------------------------------------------------------------------------
__global__ void k_bounds(const int* __restrict__ bid, int* __restrict__ start) {
    int a = blockIdx.x * blockDim.x + threadIdx.x;
    if (a > NATM) return;
    if (a == 0) {
        int c = bid[0];
        for (int b = 0; b <= c; b++) start[b] = 0;
    } else if (a == NATM) {
        int p = bid[NATM - 1];
        for (int b = p + 1; b <= NBLK; b++) start[b] = NATM;
    } else {
        int p = bid[a - 1], c = bid[a];
        for (int b = p + 1; b <= c; b++) start[b] = a;
    }
}

// ---------------------------------------------------------------------------
// segment-mean pooling: one warp per block (atoms contiguous)
// ---------------------------------------------------------------------------
__global__ void k_pool(const float* __restrict__ H, const float* __restrict__ Z,
                       const int* __restrict__ start, float* __restrict__ h,
                       float* __restrict__ zc, float* __restrict__ outHb) {
    int gt = blockIdx.x * blockDim.x + threadIdx.x;
    int b = gt >> 5;
    int lane = gt & 31;
    if (b >= NBLK) return;
    int lo = start[b], hi = start[b + 1];
    float4 hs = make_float4(0.f, 0.f, 0.f, 0.f);
    for (int a = lo; a < hi; a++) {
        float4 v = *(const float4*)&H[(size_t)a * HID + lane * 4];
        hs.x += v.x; hs.y += v.y; hs.z += v.z; hs.w += v.w;
    }
    float zx = 0.f, zy = 0.f, zz = 0.f;
    for (int a = lo + lane; a < hi; a += 32) {
        zx += Z[a * 3 + 0]; zy += Z[a * 3 + 1]; zz += Z[a * 3 + 2];
    }
#pragma unroll
    for (int o = 16; o > 0; o >>= 1) {
        zx += __shfl_xor_sync(0xffffffffu, zx, o);
        zy += __shfl_xor_sync(0xffffffffu, zy, o);
        zz += __shfl_xor_sync(0xffffffffu, zz, o);
    }
    float cnt = (float)(hi - lo);
    float inv = 1.0f / fmaxf(cnt, 1.0f);
    hs.x *= inv; hs.y *= inv; hs.z *= inv; hs.w *= inv;
    *(float4*)&h[(size_t)b * HID + lane * 4] = hs;
    *(float4*)&outHb[(size_t)b * HID + lane * 4] = hs;
    if (lane == 0) {
        zc[b * 4 + 0] = zx * inv;
        zc[b * 4 + 1] = zy * inv;
        zc[b * 4 + 2] = zz * inv;
        zc[b * 4 + 3] = cnt;
    }
}

// ---------------------------------------------------------------------------
// counting sort of edges by dst: hist -> scan (3 kernels) -> scatter
// ---------------------------------------------------------------------------
__global__ void k_hist(const int* __restrict__ edges, int* __restrict__ cnt) {
    int e = blockIdx.x * blockDim.x + threadIdx.x;
    if (e < NE) atomicAdd(&cnt[edges[NE + e]], 1);
}

__global__ void k_scan1(const int* __restrict__ cnt, int* __restrict__ offs,
                        int* __restrict__ tops) {
    __shared__ int sh[512];
    int i = blockIdx.x * 512 + threadIdx.x;
    int v = (i < NBLK) ? cnt[i] : 0;
    sh[threadIdx.x] = v;
    __syncthreads();
#pragma unroll
    for (int off = 1; off < 512; off <<= 1) {
        int t = 0;
        if (threadIdx.x >= off) t = sh[threadIdx.x - off];
        __syncthreads();
        if (threadIdx.x >= off) sh[threadIdx.x] += t;
        __syncthreads();
    }
    if (i < NBLK) offs[i] = sh[threadIdx.x] - v;
    if (threadIdx.x == 511) tops[blockIdx.x] = sh[511];
}

__global__ void k_scan2(int* __restrict__ tops) {
    __shared__ int sh[128];
    int v = (threadIdx.x < NTOPS) ? tops[threadIdx.x] : 0;
    sh[threadIdx.x] = v;
    __syncthreads();
#pragma unroll
    for (int off = 1; off < 128; off <<= 1) {
        int t = 0;
        if (threadIdx.x >= off) t = sh[threadIdx.x - off];
        __syncthreads();
        if (threadIdx.x >= off) sh[threadIdx.x] += t;
        __syncthreads();
    }
    if (threadIdx.x < NTOPS) tops[threadIdx.x] = sh[threadIdx.x] - v;
}

__global__ void k_scan3(int* __restrict__ offs, const int* __restrict__ tops) {
    int i = blockIdx.x * 512 + threadIdx.x;
    if (i < NBLK) offs[i] += tops[blockIdx.x];
}

__global__ void k_scat(const int* __restrict__ edges, int* __restrict__ offs,
                       int* __restrict__ ssrc, int* __restrict__ sdst) {
    int e = blockIdx.x * blockDim.x + threadIdx.x;
    if (e >= NE) return;
    int d = edges[NE + e];
    int pos = atomicAdd(&offs[d], 1);
    ssrc[pos] = edges[e];
    sdst[pos] = d;
}

// ---------------------------------------------------------------------------
// rbf over dst-sorted edges (tf32-rounded bits), sequential writes
// ---------------------------------------------------------------------------
__global__ void k_rbf(const int* __restrict__ ssrc, const int* __restrict__ sdst,
                      const float* __restrict__ zc, float* __restrict__ rbf) {
    int gt = blockIdx.x * blockDim.x + threadIdx.x;
    int e = gt >> 5;
    int lane = gt & 31;
    if (e >= NE) return;
    int s = ssrc[e];
    int t = sdst[e];
    float dx = zc[s * 4 + 0] - zc[t * 4 + 0];
    float dy = zc[s * 4 + 1] - zc[t * 4 + 1];
    float dz = zc[s * 4 + 2] - zc[t * 4 + 2];
    float d = sqrtf(dx * dx + dy * dy + dz * dz + 1e-12f);
    const float step = 6.0f / 63.0f;
#pragma unroll
    for (int i = 0; i < 2; i++) {
        int k = lane + 32 * i;
        float diff = d - step * (float)k;
        float v = __expf(-10.0f * diff * diff);
        rbf[(size_t)e * RAD + k] = __uint_as_float(cvt_tf32(v));
    }
}

// ---------------------------------------------------------------------------
// tf32 tensor GEMM, double-buffered: C[M,N] = A[M,K] @ B[K,N]
// BM=128 BN=64 BK=32, 256 threads. Two outputs: block.x >= ntiles0 -> (B1,C1).
// epi==1: C += silu(acc). Requires K%32==0, N%64==0.
// ---------------------------------------------------------------------------
__global__ void __launch_bounds__(256)
k_gemm(const float* __restrict__ A, const float* __restrict__ B0,
       const float* __restrict__ B1, float* __restrict__ C0,
       float* __restrict__ C1, int M, int N, int K, int epi, int ntiles0) {
    __shared__ unsigned As[128 * 36];
    __shared__ unsigned Bs[32 * 68];
    int tid = threadIdx.x;
    int warp = tid >> 5, lane = tid & 31;
    int gid = lane >> 2, tig = lane & 3;
    int wm = (warp & 3) * 32, wn = (warp >> 2) * 32;
    int rowBase = blockIdx.y * 128;
    int bx = blockIdx.x;
    const float* B = B0;
    float* C = C0;
    if (bx >= ntiles0) { B = B1; C = C1; bx -= ntiles0; }
    int colBase = bx * 64;

    int ar = tid >> 3, ac = (tid & 7) * 4;
    int br = tid >> 4, bc = (tid & 15) * 4;

    float4 av[4], bv[2];
#pragma unroll
    for (int i = 0; i < 4; i++) {
        int r = rowBase + ar + i * 32;
        av[i] = (r < M) ? *(const float4*)&A[(size_t)r * K + ac]
                        : make_float4(0.f, 0.f, 0.f, 0.f);
    }
#pragma unroll
    for (int i = 0; i < 2; i++)
        bv[i] = *(const float4*)&B[(size_t)(br + i * 16) * N + colBase + bc];

    float acc[2][4][4];
#pragma unroll
    for (int mt = 0; mt < 2; mt++)
#pragma unroll
        for (int nn = 0; nn < 4; nn++)
#pragma unroll
            for (int q = 0; q < 4; q++) acc[mt][nn][q] = 0.f;

    for (int k0 = 0; k0 < K; k0 += 32) {
#pragma unroll
        for (int i = 0; i < 4; i++) {
            uint4 u;
            u.x = cvt_tf32(av[i].x); u.y = cvt_tf32(av[i].y);
            u.z = cvt_tf32(av[i].z); u.w = cvt_tf32(av[i].w);
            *(uint4*)&As[(ar + i * 32) * 36 + ac] = u;
        }
#pragma unroll
        for (int i = 0; i < 2; i++) {
            uint4 u;
            u.x = cvt_tf32(bv[i].x); u.y = cvt_tf32(bv[i].y);
            u.z = cvt_tf32(bv[i].z); u.w = cvt_tf32(bv[i].w);
            *(uint4*)&Bs[(br + i * 16) * 68 + bc] = u;
        }
        __syncthreads();
        if (k0 + 32 < K) {
#pragma unroll
            for (int i = 0; i < 4; i++) {
                int r = rowBase + ar + i * 32;
                av[i] = (r < M)
                    ? *(const float4*)&A[(size_t)r * K + k0 + 32 + ac]
                    : make_float4(0.f, 0.f, 0.f, 0.f);
            }
#pragma unroll
            for (int i = 0; i < 2; i++)
                bv[i] = *(const float4*)
                    &B[(size_t)(k0 + 32 + br + i * 16) * N + colBase + bc];
        }
#pragma unroll
        for (int kk = 0; kk < 4; kk++) {
            unsigned a[2][4], b[4][2];
#pragma unroll
            for (int mt = 0; mt < 2; mt++) {
                int r = wm + mt * 16 + gid;
                a[mt][0] = As[r * 36 + kk * 8 + tig];
                a[mt][1] = As[(r + 8) * 36 + kk * 8 + tig];
                a[mt][2] = As[r * 36 + kk * 8 + tig + 4];
                a[mt][3] = As[(r + 8) * 36 + kk * 8 + tig + 4];
            }
#pragma unroll
            for (int nn = 0; nn < 4; nn++) {
                b[nn][0] = Bs[(kk * 8 + tig) * 68 + wn + nn * 8 + gid];
                b[nn][1] = Bs[(kk * 8 + tig + 4) * 68 + wn + nn * 8 + gid];
            }
#pragma unroll
            for (int mt = 0; mt < 2; mt++)
#pragma unroll
                for (int nn = 0; nn < 4; nn++)
                    mma_tf32(acc[mt][nn], a[mt], b[nn]);
        }
        __syncthreads();
    }

#pragma unroll
    for (int mt = 0; mt < 2; mt++) {
#pragma unroll
        for (int nn = 0; nn < 4; nn++) {
            int r0 = rowBase + wm + mt * 16 + gid;
            int r1 = r0 + 8;
            int c = colBase + wn + nn * 8 + 2 * tig;
            if (r0 < M) {
                size_t idx = (size_t)r0 * N + c;
                if (epi == 1) {
                    C[idx]     += silu_f(acc[mt][nn][0]);
                    C[idx + 1] += silu_f(acc[mt][nn][1]);
                } else {
                    C[idx]     = acc[mt][nn][0];
                    C[idx + 1] = acc[mt][nn][1];
                }
            }
            if (r1 < M) {
                size_t idx = (size_t)r1 * N + c;
                if (epi == 1) {
                    C[idx]     += silu_f(acc[mt][nn][2]);
                    C[idx + 1] += silu_f(acc[mt][nn][3]);
                } else {
                    C[idx]     = acc[mt][nn][2];
                    C[idx + 1] = acc[mt][nn][3];
                }
            }
        }
    }
}

// ---------------------------------------------------------------------------
// edge message kernel over dst-sorted edges, 32-edge tiles.
// raw = A[src] + B[dst] + rbf@Wc  (mma);  segmented reduce of silu(raw) by dst
// with one red.v4 per run per 8-row sub-tile.
// ---------------------------------------------------------------------------
__global__ void __launch_bounds__(256)
k_edge_tc(const int* __restrict__ ssrc, const int* __restrict__ sdst,
          const float* __restrict__ Wcl, const float* __restrict__ Ag,
          const float* __restrict__ Bg, const float* __restrict__ rbf,
          float* __restrict__ agg) {
    int tid = threadIdx.x;
    int warp = tid >> 5, lane = tid & 31;
    int gid = lane >> 2, tig = lane & 3;
    int nb = warp * 32;

    unsigned bfr[8][4][2];
#pragma unroll
    for (int kk = 0; kk < 8; kk++)
#pragma unroll
        for (int nn = 0; nn < 4; nn++) {
            bfr[kk][nn][0] =
                cvt_tf32(Wcl[(kk * 8 + tig) * 256 + nb + nn * 8 + gid]);
            bfr[kk][nn][1] =
                cvt_tf32(Wcl[(kk * 8 + tig + 4) * 256 + nb + nn * 8 + gid]);
        }

    __shared__ unsigned rbs[32 * 68];
    __shared__ float Gs[32 * 260];
    __shared__ int ss[32], ds[32];

    const int nG = (NE + 31) / 32;
    for (int g = blockIdx.x; g < nG; g += gridDim.x) {
        int base = g * 32;
        if (tid < 32) {
            int e = base + tid;
            ss[tid] = (e < NE) ? ssrc[e] : 0;
            ds[tid] = (e < NE) ? sdst[e] : -1;
        }
#pragma unroll
        for (int i = 0; i < 2; i++) {
            int idx = tid + i * 256;
            int r = idx >> 4;
            int c4 = (idx & 15) * 4;
            int e = base + r;
            float4 v = make_float4(0.f, 0.f, 0.f, 0.f);
            if (e < NE) v = *(const float4*)&rbf[(size_t)e * 64 + c4];
            *(uint4*)&rbs[r * 68 + c4] = *(uint4*)&v;
        }
        __syncthreads();
#pragma unroll
        for (int i = 0; i < 8; i++) {
            int idx = tid + i * 256;
            int r = idx >> 6;
            int c4 = (idx & 63) * 4;
            int s = ss[r];
            int d = ds[r];
            int dg = d < 0 ? 0 : d;
            float4 a = *(const float4*)&Ag[(size_t)s * 256 + c4];
            float4 b = *(const float4*)&Bg[(size_t)dg * 256 + c4];
            float4 t;
            t.x = a.x + b.x; t.y = a.y + b.y;
            t.z = a.z + b.z; t.w = a.w + b.w;
            *(float4*)&Gs[r * 260 + c4] = t;
        }
        __syncthreads();

        float acc[2][4][4];
#pragma unroll
        for (int mt = 0; mt < 2; mt++)
#pragma unroll
            for (int nn = 0; nn < 4; nn++)
#pragma unroll
                for (int q = 0; q < 4; q++) acc[mt][nn][q] = 0.f;

#pragma unroll
        for (int kk = 0; kk < 8; kk++) {
            unsigned a[2][4];
#pragma unroll
            for (int mt = 0; mt < 2; mt++) {
                int r = mt * 16 + gid;
                a[mt][0] = rbs[r * 68 + kk * 8 + tig];
                a[mt][1] = rbs[(r + 8) * 68 + kk * 8 + tig];
                a[mt][2] = rbs[r * 68 + kk * 8 + tig + 4];
                a[mt][3] = rbs[(r + 8) * 68 + kk * 8 + tig + 4];
            }
#pragma unroll
            for (int mt = 0; mt < 2; mt++)
#pragma unroll
                for (int nn = 0; nn < 4; nn++)
                    mma_tf32(acc[mt][nn], a[mt], bfr[kk][nn]);
        }

        // store raw (pre-silu) back to Gs
#pragma unroll
        for (int mt = 0; mt < 2; mt++) {
#pragma unroll
            for (int nn = 0; nn < 4; nn++) {
                int r0 = mt * 16 + gid;
                int r1 = r0 + 8;
                int c = nb + nn * 8 + 2 * tig;
                Gs[r0 * 260 + c]     += acc[mt][nn][0];
                Gs[r0 * 260 + c + 1] += acc[mt][nn][1];
                Gs[r1 * 260 + c]     += acc[mt][nn][2];
                Gs[r1 * 260 + c + 1] += acc[mt][nn][3];
            }
        }
        __syncthreads();

        // segmented reduce (silu fused), 8 rows per thread, 64 column-quads
        {
            int q = tid & 63;
            int c4 = q * 4;
            int rsub = (tid >> 6) * 8;
            float4 a4 = make_float4(0.f, 0.f, 0.f, 0.f);
            int cur = -1;
#pragma unroll
            for (int r = rsub; r < rsub + 8; r++) {
                int d = ds[r];
                if (d != cur) {
                    if (cur >= 0) red4(&agg[(size_t)cur * 256 + c4], a4);
                    a4 = make_float4(0.f, 0.f, 0.f, 0.f);
                    cur = d;
                }
                if (d >= 0) {
                    float4 m = *(float4*)&Gs[r * 260 + c4];
                    a4.x += silu_f(m.x); a4.y += silu_f(m.y);
                    a4.z += silu_f(m.z); a4.w += silu_f(m.w);
                }
            }
            if (cur >= 0) red4(&agg[(size_t)cur * 256 + c4], a4);
        }
        __syncthreads();
    }
}

// ---------------------------------------------------------------------------
__global__ void k_rownorm_scatter(const float* __restrict__ tmp,
                                  const int* __restrict__ batch_id,
                                  float* __restrict__ out_block,
                                  float* __restrict__ gacc) {
    int gt = blockIdx.x * blockDim.x + threadIdx.x;
    int r = gt >> 5;
    int lane = gt & 31;
    if (r >= NBLK) return;
    float4 v = *(const float4*)&tmp[(size_t)r * HID + lane * 4];
    float ss = v.x * v.x + v.y * v.y + v.z * v.z + v.w * v.w;
#pragma unroll
    for (int o = 16; o > 0; o >>= 1) ss += __shfl_xor_sync(0xffffffffu, ss, o);
    float inv = 1.0f / fmaxf(sqrtf(ss), 1e-12f);
    int g = batch_id[r];
    float4 nv = make_float4(v.x * inv, v.y * inv, v.z * inv, v.w * inv);
    *(float4*)&out_block[(size_t)r * HID + lane * 4] = nv;
    red4(&gacc[g * HID + lane * 4], nv);
}

__global__ void k_graphnorm(const float* __restrict__ gacc,
                            float* __restrict__ out_graph) {
    int gt = blockIdx.x * blockDim.x + threadIdx.x;
    int r = gt >> 5;
    int lane = gt & 31;
    if (r >= NG) return;
    float4 v = *(const float4*)&gacc[r * HID + lane * 4];
    float ss = v.x * v.x + v.y * v.y + v.z * v.z + v.w * v.w;
#pragma unroll
    for (int o = 16; o > 0; o >>= 1) ss += __shfl_xor_sync(0xffffffffu, ss, o);
    float inv = 1.0f / fmaxf(sqrtf(ss), 1e-12f);
    float4 nv = make_float4(v.x * inv, v.y * inv, v.z * inv, v.w * inv);
    *(float4*)&out_graph[r * HID + lane * 4] = nv;
}

// ---------------------------------------------------------------------------
extern "C" void kernel_launch(void* const* d_in, const int* in_sizes, int n_in,
                              void* d_out, int out_size) {
    const float* H      = (const float*)d_in[0];
    const float* Z      = (const float*)d_in[1];
    const float* W_rbf  = (const float*)d_in[2];
    const float* Wm1    = (const float*)d_in[3];
    const float* Wm2    = (const float*)d_in[4];
    const float* We     = (const float*)d_in[5];
    const float* Wupd   = (const float*)d_in[6];
    const float* W_out  = (const float*)d_in[7];
    const int*   block_id = (const int*)d_in[8];
    const int*   batch_id = (const int*)d_in[9];
    const int*   edges    = (const int*)d_in[10];

    float* out = (float*)d_out;
    float* out_Hb    = out;
    float* out_block = out + (size_t)NBLK * HID;
    float* out_graph = out + 2 * (size_t)NBLK * HID;

    void* scrv = nullptr;
    cudaGetSymbolAddress(&scrv, g_scratch);
    float* scr  = (float*)scrv;
    float* s_h    = scr + OFF_H;
    float* s_zc   = scr + OFF_ZC;
    float* s_A    = scr + OFF_A;
    float* s_B    = scr + OFF_B;
    float* s_agg  = scr + OFF_AGG;
    float* s_rbf  = scr + OFF_RBF;
    float* s_Wc   = scr + OFF_WC;
    float* s_gacc = scr + OFF_GACC;
    int*   s_start = (int*)(scr + OFF_START);
    int*   s_cnt   = (int*)(scr + OFF_CNT);
    int*   s_tops  = (int*)(scr + OFF_TOPS);
    int*   s_ssrc  = (int*)(scr + OFF_SSRC);
    int*   s_sdst  = (int*)(scr + OFF_SDST);

    // Wc[l] = W_rbf @ We[l] (independent of everything else)
    for (int l = 0; l < NLAY; l++) {
        k_gemm<<<dim3(4, 1), 256>>>(W_rbf, We + (size_t)l * 256 * 256, nullptr,
                                    s_Wc + (size_t)l * 64 * 256, nullptr,
                                    64, 256, 256, 0, 4);
    }

    // pooling via sorted segments
    k_bounds<<<(NATM + 256) / 256, 256>>>(block_id, s_start);
    k_pool<<<(NBLK * 32 + 255) / 256, 256>>>(H, Z, s_start, s_h, s_zc, out_Hb);

    // counting sort of edges by dst
    k_zero4<<<32, 256>>>((float*)s_cnt, 50016 / 4);
    k_hist<<<(NE + 255) / 256, 256>>>(edges, s_cnt);
    k_scan1<<<NTOPS, 512>>>(s_cnt, s_cnt, s_tops);   // in-place excl scan ok? no:
    // NOTE: k_scan1 reads cnt[i] then writes offs[i]=excl — same array is safe
    // because each thread reads its own element before writing it.
    k_scan2<<<1, 128>>>(s_tops);
    k_scan3<<<NTOPS, 512>>>(s_cnt, s_tops);
    k_scat<<<(NE + 255) / 256, 256>>>(edges, s_cnt, s_ssrc, s_sdst);

    // rbf in sorted order
    k_rbf<<<(NE * 32 + 255) / 256, 256>>>(s_ssrc, s_sdst, s_zc, s_rbf);

    // zero graph accumulator
    k_zero4<<<8, 256>>>(s_gacc, (NG * HID) / 4);

    dim3 gridAB(8, (NBLK + 127) / 128);
    dim3 gridUpd(2, (NBLK + 127) / 128);

    for (int l = 0; l < NLAY; l++) {
        // A = h@Wm1[l], B = h@Wm2[l] in one launch
        k_gemm<<<gridAB, 256>>>(s_h, Wm1 + (size_t)l * HID * EDGEF,
                                Wm2 + (size_t)l * HID * EDGEF, s_A, s_B,
                                NBLK, EDGEF, HID, 0, 4);
        k_zero4<<<8192, 256>>>(s_agg, (NBLK * EDGEF) / 4);
        k_edge_tc<<<2048, 256>>>(s_ssrc, s_sdst, s_Wc + (size_t)l * 64 * 256,
                                 s_A, s_B, s_rbf, s_agg);
        k_gemm<<<gridUpd, 256>>>(s_agg, Wupd + (size_t)l * EDGEF * HID, nullptr,
                                 s_h, nullptr, NBLK, HID, EDGEF, 1, 2);
    }

    // block_repr = l2norm(h @ W_out)
    k_gemm<<<gridUpd, 256>>>(s_h, W_out, nullptr, s_A, nullptr,
                             NBLK, HID, HID, 0, 2);
    k_rownorm_scatter<<<(NBLK * 32 + 255) / 256, 256>>>(s_A, batch_id,
                                                        out_block, s_gacc);
    k_graphnorm<<<(NG * 32 + 255) / 256, 256>>>(s_gacc, out_graph);
}

// round 4
// speedup vs baseline: 2.0517x; 1.0000x over previous
#include <cuda_runtime.h>
#include <cuda_bf16.h>
#include <math.h>

#define NATM 200000
#define NBLK 50000
#define NE   450000
#define NG   64
#define HID  128
#define RAD  64
#define EDGEF 256
#define NLAY 3

// ---- scratch layout (single __device__ buffer, floats) ----
static const size_t OFF_H     = 0;          // [NBLK*128]
static const size_t OFF_ZC    = 6400000;    // [NBLK*4] z0,z1,z2,cnt
static const size_t OFF_A     = 6600000;    // [NBLK*256]
static const size_t OFF_B     = 19400000;   // [NBLK*256]
static const size_t OFF_AGG   = 32200000;   // [NBLK*256]
static const size_t OFF_RBF   = 45000000;   // [NE*64]
static const size_t OFF_WC    = 73800000;   // [3*64*256]
static const size_t OFF_GACC  = 73849152;   // [64*128]
static const size_t OFF_START = 73857344;   // int[NBLK+1] (50016)
static const size_t OFF_CNT   = 73907360;   // int[NBLK]   (50016)
static const size_t OFF_TOPS  = 73957376;   // int[128]
static const size_t OFF_SSRC  = 73957504;   // int[NE]     (450016)
static const size_t OFF_SDST  = 74407520;   // int[NE]     (450016)
static const size_t SCR_TOTAL = 74857536;

__device__ __align__(16) float g_scratch[SCR_TOTAL];

#define NTOPS 98   // ceil(NBLK/512)

__device__ __forceinline__ float silu_f(float x) {
    return x / (1.0f + __expf(-x));
}

__device__ __forceinline__ unsigned cvt_tf32(float f) {
    unsigned u;
    asm("cvt.rna.tf32.f32 %0, %1;" : "=r"(u) : "f"(f));
    return u;
}

__device__ __forceinline__ void mma_tf32(float* c, const unsigned* a,
                                         const unsigned* b) {
    asm volatile(
        "mma.sync.aligned.m16n8k8.row.col.f32.tf32.tf32.f32 "
        "{%0,%1,%2,%3}, {%4,%5,%6,%7}, {%8,%9}, {%0,%1,%2,%3};"
        : "+f"(c[0]), "+f"(c[1]), "+f"(c[2]), "+f"(c[3])
        : "r"(a[0]), "r"(a[1]), "r"(a[2]), "r"(a[3]), "r"(b[0]), "r"(b[1]));
}

__device__ __forceinline__ void red4(float* p, float4 v) {
    asm volatile("red.global.add.v4.f32 [%0], {%1,%2,%3,%4};"
                 :: "l"(p), "f"(v.x), "f"(v.y), "f"(v.z), "f"(v.w)
                 : "memory");
}

// ---------------------------------------------------------------------------
__global__ void k_zero4(float* __restrict__ p, int n4) {
    float4 z = make_float4(0.f, 0.f, 0.f, 0.f);
    for (int i = blockIdx.x * blockDim.x + threadIdx.x; i < n4;
         i += gridDim.x * blockDim.x) {
        ((float4*)p)[i] = z;
    }
}

// ---------------------------------------------------------------------------
// segment boundaries of sorted block_id: start[b] = first atom with bid >= b
// ---------------------------------------------------------------------------
__global__ void k_bounds(const int* __restrict__ bid, int* __restrict__ start) {
    int a = blockIdx.x * blockDim.x + threadIdx.x;
    if (a > NATM) return;
    if (a == 0) {
        int c = bid[0];
        for (int b = 0; b <= c; b++) start[b] = 0;
    } else if (a == NATM) {
        int p = bid[NATM - 1];
        for (int b = p + 1; b <= NBLK; b++) start[b] = NATM;
    } else {
        int p = bid[a - 1], c = bid[a];
        for (int b = p + 1; b <= c; b++) start[b] = a;
    }
}

// ---------------------------------------------------------------------------
// segment-mean pooling: one warp per block (atoms contiguous)
// ---------------------------------------------------------------------------
__global__ void k_pool(const float* __restrict__ H, const float* __restrict__ Z,
                       const int* __restrict__ start, float* __restrict__ h,
                       float* __restrict__ zc, float* __restrict__ outHb) {
    int gt = blockIdx.x * blockDim.x + threadIdx.x;
    int b = gt >> 5;
    int lane = gt & 31;
    if (b >= NBLK) return;
    int lo = start[b], hi = start[b + 1];
    float4 hs = make_float4(0.f, 0.f, 0.f, 0.f);
    for (int a = lo; a < hi; a++) {
        float4 v = *(const float4*)&H[(size_t)a * HID + lane * 4];
        hs.x += v.x; hs.y += v.y; hs.z += v.z; hs.w += v.w;
    }
    float zx = 0.f, zy = 0.f, zz = 0.f;
    for (int a = lo + lane; a < hi; a += 32) {
        zx += Z[a * 3 + 0]; zy += Z[a * 3 + 1]; zz += Z[a * 3 + 2];
    }
#pragma unroll
    for (int o = 16; o > 0; o >>= 1) {
        zx += __shfl_xor_sync(0xffffffffu, zx, o);
        zy += __shfl_xor_sync(0xffffffffu, zy, o);
        zz += __shfl_xor_sync(0xffffffffu, zz, o);
    }
    float cnt = (float)(hi - lo);
    float inv = 1.0f / fmaxf(cnt, 1.0f);
    hs.x *= inv; hs.y *= inv; hs.z *= inv; hs.w *= inv;
    *(float4*)&h[(size_t)b * HID + lane * 4] = hs;
    *(float4*)&outHb[(size_t)b * HID + lane * 4] = hs;
    if (lane == 0) {
        zc[b * 4 + 0] = zx * inv;
        zc[b * 4 + 1] = zy * inv;
        zc[b * 4 + 2] = zz * inv;
        zc[b * 4 + 3] = cnt;
    }
}

// ---------------------------------------------------------------------------
// counting sort of edges by dst: hist -> scan (3 kernels) -> scatter
// ---------------------------------------------------------------------------
__global__ void k_hist(const int* __restrict__ edges, int* __restrict__ cnt) {
    int e = blockIdx.x * blockDim.x + threadIdx.x;
    if (e < NE) atomicAdd(&cnt[edges[NE + e]], 1);
}

__global__ void k_scan1(const int* __restrict__ cnt, int* __restrict__ offs,
                        int* __restrict__ tops) {
    __shared__ int sh[512];
    int i = blockIdx.x * 512 + threadIdx.x;
    int v = (i < NBLK) ? cnt[i] : 0;
    sh[threadIdx.x] = v;
    __syncthreads();
#pragma unroll
    for (int off = 1; off < 512; off <<= 1) {
        int t = 0;
        if (threadIdx.x >= off) t = sh[threadIdx.x - off];
        __syncthreads();
        if (threadIdx.x >= off) sh[threadIdx.x] += t;
        __syncthreads();
    }
    if (i < NBLK) offs[i] = sh[threadIdx.x] - v;
    if (threadIdx.x == 511) tops[blockIdx.x] = sh[511];
}

__global__ void k_scan2(int* __restrict__ tops) {
    __shared__ int sh[128];
    int v = (threadIdx.x < NTOPS) ? tops[threadIdx.x] : 0;
    sh[threadIdx.x] = v;
    __syncthreads();
#pragma unroll
    for (int off = 1; off < 128; off <<= 1) {
        int t = 0;
        if (threadIdx.x >= off) t = sh[threadIdx.x - off];
        __syncthreads();
        if (threadIdx.x >= off) sh[threadIdx.x] += t;
        __syncthreads();
    }
    if (threadIdx.x < NTOPS) tops[threadIdx.x] = sh[threadIdx.x] - v;
}

__global__ void k_scan3(int* __restrict__ offs, const int* __restrict__ tops) {
    int i = blockIdx.x * 512 + threadIdx.x;
    if (i < NBLK) offs[i] += tops[blockIdx.x];
}

__global__ void k_scat(const int* __restrict__ edges, int* __restrict__ offs,
                       int* __restrict__ ssrc, int* __restrict__ sdst) {
    int e = blockIdx.x * blockDim.x + threadIdx.x;
    if (e >= NE) return;
    int d = edges[NE + e];
    int pos = atomicAdd(&offs[d], 1);
    ssrc[pos] = edges[e];
    sdst[pos] = d;
}

// ---------------------------------------------------------------------------
// rbf over dst-sorted edges (tf32-rounded bits), sequential writes
// ---------------------------------------------------------------------------
__global__ void k_rbf(const int* __restrict__ ssrc, const int* __restrict__ sdst,
                      const float* __restrict__ zc, float* __restrict__ rbf) {
    int gt = blockIdx.x * blockDim.x + threadIdx.x;
    int e = gt >> 5;
    int lane = gt & 31;
    if (e >= NE) return;
    int s = ssrc[e];
    int t = sdst[e];
    float dx = zc[s * 4 + 0] - zc[t * 4 + 0];
    float dy = zc[s * 4 + 1] - zc[t * 4 + 1];
    float dz = zc[s * 4 + 2] - zc[t * 4 + 2];
    float d = sqrtf(dx * dx + dy * dy + dz * dz + 1e-12f);
    const float step = 6.0f / 63.0f;
#pragma unroll
    for (int i = 0; i < 2; i++) {
        int k = lane + 32 * i;
        float diff = d - step * (float)k;
        float v = __expf(-10.0f * diff * diff);
        rbf[(size_t)e * RAD + k] = __uint_as_float(cvt_tf32(v));
    }
}

// ---------------------------------------------------------------------------
// tf32 tensor GEMM, double-buffered: C[M,N] = A[M,K] @ B[K,N]
// BM=128 BN=64 BK=32, 256 threads. Two outputs: block.x >= ntiles0 -> (B1,C1).
// epi==1: C += silu(acc). Requires K%32==0, N%64==0.
// ---------------------------------------------------------------------------
__global__ void __launch_bounds__(256)
k_gemm(const float* __restrict__ A, const float* __restrict__ B0,
       const float* __restrict__ B1, float* __restrict__ C0,
       float* __restrict__ C1, int M, int N, int K, int epi, int ntiles0) {
    __shared__ unsigned As[128 * 36];
    __shared__ unsigned Bs[32 * 68];
    int tid = threadIdx.x;
    int warp = tid >> 5, lane = tid & 31;
    int gid = lane >> 2, tig = lane & 3;
    int wm = (warp & 3) * 32, wn = (warp >> 2) * 32;
    int rowBase = blockIdx.y * 128;
    int bx = blockIdx.x;
    const float* B = B0;
    float* C = C0;
    if (bx >= ntiles0) { B = B1; C = C1; bx -= ntiles0; }
    int colBase = bx * 64;

    int ar = tid >> 3, ac = (tid & 7) * 4;
    int br = tid >> 4, bc = (tid & 15) * 4;

    float4 av[4], bv[2];
#pragma unroll
    for (int i = 0; i < 4; i++) {
        int r = rowBase + ar + i * 32;
        av[i] = (r < M) ? *(const float4*)&A[(size_t)r * K + ac]
                        : make_float4(0.f, 0.f, 0.f, 0.f);
    }
#pragma unroll
    for (int i = 0; i < 2; i++)
        bv[i] = *(const float4*)&B[(size_t)(br + i * 16) * N + colBase + bc];

    float acc[2][4][4];
#pragma unroll
    for (int mt = 0; mt < 2; mt++)
#pragma unroll
        for (int nn = 0; nn < 4; nn++)
#pragma unroll
            for (int q = 0; q < 4; q++) acc[mt][nn][q] = 0.f;

    for (int k0 = 0; k0 < K; k0 += 32) {
#pragma unroll
        for (int i = 0; i < 4; i++) {
            uint4 u;
            u.x = cvt_tf32(av[i].x); u.y = cvt_tf32(av[i].y);
            u.z = cvt_tf32(av[i].z); u.w = cvt_tf32(av[i].w);
            *(uint4*)&As[(ar + i * 32) * 36 + ac] = u;
        }
#pragma unroll
        for (int i = 0; i < 2; i++) {
            uint4 u;
            u.x = cvt_tf32(bv[i].x); u.y = cvt_tf32(bv[i].y);
            u.z = cvt_tf32(bv[i].z); u.w = cvt_tf32(bv[i].w);
            *(uint4*)&Bs[(br + i * 16) * 68 + bc] = u;
        }
        __syncthreads();
        if (k0 + 32 < K) {
#pragma unroll
            for (int i = 0; i < 4; i++) {
                int r = rowBase + ar + i * 32;
                av[i] = (r < M)
                    ? *(const float4*)&A[(size_t)r * K + k0 + 32 + ac]
                    : make_float4(0.f, 0.f, 0.f, 0.f);
            }
#pragma unroll
            for (int i = 0; i < 2; i++)
                bv[i] = *(const float4*)
                    &B[(size_t)(k0 + 32 + br + i * 16) * N + colBase + bc];
        }
#pragma unroll
        for (int kk = 0; kk < 4; kk++) {
            unsigned a[2][4], b[4][2];
#pragma unroll
            for (int mt = 0; mt < 2; mt++) {
                int r = wm + mt * 16 + gid;
                a[mt][0] = As[r * 36 + kk * 8 + tig];
                a[mt][1] = As[(r + 8) * 36 + kk * 8 + tig];
                a[mt][2] = As[r * 36 + kk * 8 + tig + 4];
                a[mt][3] = As[(r + 8) * 36 + kk * 8 + tig + 4];
            }
#pragma unroll
            for (int nn = 0; nn < 4; nn++) {
                b[nn][0] = Bs[(kk * 8 + tig) * 68 + wn + nn * 8 + gid];
                b[nn][1] = Bs[(kk * 8 + tig + 4) * 68 + wn + nn * 8 + gid];
            }
#pragma unroll
            for (int mt = 0; mt < 2; mt++)
#pragma unroll
                for (int nn = 0; nn < 4; nn++)
                    mma_tf32(acc[mt][nn], a[mt], b[nn]);
        }
        __syncthreads();
    }

#pragma unroll
    for (int mt = 0; mt < 2; mt++) {
#pragma unroll
        for (int nn = 0; nn < 4; nn++) {
            int r0 = rowBase + wm + mt * 16 + gid;
            int r1 = r0 + 8;
            int c = colBase + wn + nn * 8 + 2 * tig;
            if (r0 < M) {
                size_t idx = (size_t)r0 * N + c;
                if (epi == 1) {
                    C[idx]     += silu_f(acc[mt][nn][0]);
                    C[idx + 1] += silu_f(acc[mt][nn][1]);
                } else {
                    C[idx]     = acc[mt][nn][0];
                    C[idx + 1] = acc[mt][nn][1];
                }
            }
            if (r1 < M) {
                size_t idx = (size_t)r1 * N + c;
                if (epi == 1) {
                    C[idx]     += silu_f(acc[mt][nn][2]);
                    C[idx + 1] += silu_f(acc[mt][nn][3]);
                } else {
                    C[idx]     = acc[mt][nn][2];
                    C[idx + 1] = acc[mt][nn][3];
                }
            }
        }
    }
}

// ---------------------------------------------------------------------------
// edge message kernel over dst-sorted edges, 32-edge tiles.
// raw = A[src] + B[dst] + rbf@Wc  (mma);  segmented reduce of silu(raw) by dst
// with one red.v4 per run per 8-row sub-tile.
// ---------------------------------------------------------------------------
__global__ void __launch_bounds__(256)
k_edge_tc(const int* __restrict__ ssrc, const int* __restrict__ sdst,
          const float* __restrict__ Wcl, const float* __restrict__ Ag,
          const float* __restrict__ Bg, const float* __restrict__ rbf,
          float* __restrict__ agg) {
    int tid = threadIdx.x;
    int warp = tid >> 5, lane = tid & 31;
    int gid = lane >> 2, tig = lane & 3;
    int nb = warp * 32;

    unsigned bfr[8][4][2];
#pragma unroll
    for (int kk = 0; kk < 8; kk++)
#pragma unroll
        for (int nn = 0; nn < 4; nn++) {
            bfr[kk][nn][0] =
                cvt_tf32(Wcl[(kk * 8 + tig) * 256 + nb + nn * 8 + gid]);
            bfr[kk][nn][1] =
                cvt_tf32(Wcl[(kk * 8 + tig + 4) * 256 + nb + nn * 8 + gid]);
        }

    __shared__ unsigned rbs[32 * 68];
    __shared__ float Gs[32 * 260];
    __shared__ int ss[32], ds[32];

    const int nG = (NE + 31) / 32;
    for (int g = blockIdx.x; g < nG; g += gridDim.x) {
        int base = g * 32;
        if (tid < 32) {
            int e = base + tid;
            ss[tid] = (e < NE) ? ssrc[e] : 0;
            ds[tid] = (e < NE) ? sdst[e] : -1;
        }
#pragma unroll
        for (int i = 0; i < 2; i++) {
            int idx = tid + i * 256;
            int r = idx >> 4;
            int c4 = (idx & 15) * 4;
            int e = base + r;
            float4 v = make_float4(0.f, 0.f, 0.f, 0.f);
            if (e < NE) v = *(const float4*)&rbf[(size_t)e * 64 + c4];
            *(uint4*)&rbs[r * 68 + c4] = *(uint4*)&v;
        }
        __syncthreads();
#pragma unroll
        for (int i = 0; i < 8; i++) {
            int idx = tid + i * 256;
            int r = idx >> 6;
            int c4 = (idx & 63) * 4;
            int s = ss[r];
            int d = ds[r];
            int dg = d < 0 ? 0 : d;
            float4 a = *(const float4*)&Ag[(size_t)s * 256 + c4];
            float4 b = *(const float4*)&Bg[(size_t)dg * 256 + c4];
            float4 t;
            t.x = a.x + b.x; t.y = a.y + b.y;
            t.z = a.z + b.z; t.w = a.w + b.w;
            *(float4*)&Gs[r * 260 + c4] = t;
        }
        __syncthreads();

        float acc[2][4][4];
#pragma unroll
        for (int mt = 0; mt < 2; mt++)
#pragma unroll
            for (int nn = 0; nn < 4; nn++)
#pragma unroll
                for (int q = 0; q < 4; q++) acc[mt][nn][q] = 0.f;

#pragma unroll
        for (int kk = 0; kk < 8; kk++) {
            unsigned a[2][4];
#pragma unroll
            for (int mt = 0; mt < 2; mt++) {
                int r = mt * 16 + gid;
                a[mt][0] = rbs[r * 68 + kk * 8 + tig];
                a[mt][1] = rbs[(r + 8) * 68 + kk * 8 + tig];
                a[mt][2] = rbs[r * 68 + kk * 8 + tig + 4];
                a[mt][3] = rbs[(r + 8) * 68 + kk * 8 + tig + 4];
            }
#pragma unroll
            for (int mt = 0; mt < 2; mt++)
#pragma unroll
                for (int nn = 0; nn < 4; nn++)
                    mma_tf32(acc[mt][nn], a[mt], bfr[kk][nn]);
        }

        // store raw (pre-silu) back to Gs
#pragma unroll
        for (int mt = 0; mt < 2; mt++) {
#pragma unroll
            for (int nn = 0; nn < 4; nn++) {
                int r0 = mt * 16 + gid;
                int r1 = r0 + 8;
                int c = nb + nn * 8 + 2 * tig;
                Gs[r0 * 260 + c]     += acc[mt][nn][0];
                Gs[r0 * 260 + c + 1] += acc[mt][nn][1];
                Gs[r1 * 260 + c]     += acc[mt][nn][2];
                Gs[r1 * 260 + c + 1] += acc[mt][nn][3];
            }
        }
        __syncthreads();

        // segmented reduce (silu fused), 8 rows per thread, 64 column-quads
        {
            int q = tid & 63;
            int c4 = q * 4;
            int rsub = (tid >> 6) * 8;
            float4 a4 = make_float4(0.f, 0.f, 0.f, 0.f);
            int cur = -1;
#pragma unroll
            for (int r = rsub; r < rsub + 8; r++) {
                int d = ds[r];
                if (d != cur) {
                    if (cur >= 0) red4(&agg[(size_t)cur * 256 + c4], a4);
                    a4 = make_float4(0.f, 0.f, 0.f, 0.f);
                    cur = d;
                }
                if (d >= 0) {
                    float4 m = *(float4*)&Gs[r * 260 + c4];
                    a4.x += silu_f(m.x); a4.y += silu_f(m.y);
                    a4.z += silu_f(m.z); a4.w += silu_f(m.w);
                }
            }
            if (cur >= 0) red4(&agg[(size_t)cur * 256 + c4], a4);
        }
        __syncthreads();
    }
}

// ---------------------------------------------------------------------------
__global__ void k_rownorm_scatter(const float* __restrict__ tmp,
                                  const int* __restrict__ batch_id,
                                  float* __restrict__ out_block,
                                  float* __restrict__ gacc) {
    int gt = blockIdx.x * blockDim.x + threadIdx.x;
    int r = gt >> 5;
    int lane = gt & 31;
    if (r >= NBLK) return;
    float4 v = *(const float4*)&tmp[(size_t)r * HID + lane * 4];
    float ss = v.x * v.x + v.y * v.y + v.z * v.z + v.w * v.w;
#pragma unroll
    for (int o = 16; o > 0; o >>= 1) ss += __shfl_xor_sync(0xffffffffu, ss, o);
    float inv = 1.0f / fmaxf(sqrtf(ss), 1e-12f);
    int g = batch_id[r];
    float4 nv = make_float4(v.x * inv, v.y * inv, v.z * inv, v.w * inv);
    *(float4*)&out_block[(size_t)r * HID + lane * 4] = nv;
    red4(&gacc[g * HID + lane * 4], nv);
}

__global__ void k_graphnorm(const float* __restrict__ gacc,
                            float* __restrict__ out_graph) {
    int gt = blockIdx.x * blockDim.x + threadIdx.x;
    int r = gt >> 5;
    int lane = gt & 31;
    if (r >= NG) return;
    float4 v = *(const float4*)&gacc[r * HID + lane * 4];
    float ss = v.x * v.x + v.y * v.y + v.z * v.z + v.w * v.w;
#pragma unroll
    for (int o = 16; o > 0; o >>= 1) ss += __shfl_xor_sync(0xffffffffu, ss, o);
    float inv = 1.0f / fmaxf(sqrtf(ss), 1e-12f);
    float4 nv = make_float4(v.x * inv, v.y * inv, v.z * inv, v.w * inv);
    *(float4*)&out_graph[r * HID + lane * 4] = nv;
}

// ---------------------------------------------------------------------------
extern "C" void kernel_launch(void* const* d_in, const int* in_sizes, int n_in,
                              void* d_out, int out_size) {
    const float* H      = (const float*)d_in[0];
    const float* Z      = (const float*)d_in[1];
    const float* W_rbf  = (const float*)d_in[2];
    const float* Wm1    = (const float*)d_in[3];
    const float* Wm2    = (const float*)d_in[4];
    const float* We     = (const float*)d_in[5];
    const float* Wupd   = (const float*)d_in[6];
    const float* W_out  = (const float*)d_in[7];
    const int*   block_id = (const int*)d_in[8];
    const int*   batch_id = (const int*)d_in[9];
    const int*   edges    = (const int*)d_in[10];

    float* out = (float*)d_out;
    float* out_Hb    = out;
    float* out_block = out + (size_t)NBLK * HID;
    float* out_graph = out + 2 * (size_t)NBLK * HID;

    void* scrv = nullptr;
    cudaGetSymbolAddress(&scrv, g_scratch);
    float* scr  = (float*)scrv;
    float* s_h    = scr + OFF_H;
    float* s_zc   = scr + OFF_ZC;
    float* s_A    = scr + OFF_A;
    float* s_B    = scr + OFF_B;
    float* s_agg  = scr + OFF_AGG;
    float* s_rbf  = scr + OFF_RBF;
    float* s_Wc   = scr + OFF_WC;
    float* s_gacc = scr + OFF_GACC;
    int*   s_start = (int*)(scr + OFF_START);
    int*   s_cnt   = (int*)(scr + OFF_CNT);
    int*   s_tops  = (int*)(scr + OFF_TOPS);
    int*   s_ssrc  = (int*)(scr + OFF_SSRC);
    int*   s_sdst  = (int*)(scr + OFF_SDST);

    // Wc[l] = W_rbf @ We[l] (independent of everything else)
    for (int l = 0; l < NLAY; l++) {
        k_gemm<<<dim3(4, 1), 256>>>(W_rbf, We + (size_t)l * 256 * 256, nullptr,
                                    s_Wc + (size_t)l * 64 * 256, nullptr,
                                    64, 256, 256, 0, 4);
    }

    // pooling via sorted segments
    k_bounds<<<(NATM + 256) / 256, 256>>>(block_id, s_start);
    k_pool<<<(NBLK * 32 + 255) / 256, 256>>>(H, Z, s_start, s_h, s_zc, out_Hb);

    // counting sort of edges by dst
    k_zero4<<<32, 256>>>((float*)s_cnt, 50016 / 4);
    k_hist<<<(NE + 255) / 256, 256>>>(edges, s_cnt);
    k_scan1<<<NTOPS, 512>>>(s_cnt, s_cnt, s_tops);   // in-place excl scan ok? no:
    // NOTE: k_scan1 reads cnt[i] then writes offs[i]=excl — same array is safe
    // because each thread reads its own element before writing it.
    k_scan2<<<1, 128>>>(s_tops);
    k_scan3<<<NTOPS, 512>>>(s_cnt, s_tops);
    k_scat<<<(NE + 255) / 256, 256>>>(edges, s_cnt, s_ssrc, s_sdst);

    // rbf in sorted order
    k_rbf<<<(NE * 32 + 255) / 256, 256>>>(s_ssrc, s_sdst, s_zc, s_rbf);

    // zero graph accumulator
    k_zero4<<<8, 256>>>(s_gacc, (NG * HID) / 4);

    dim3 gridAB(8, (NBLK + 127) / 128);
    dim3 gridUpd(2, (NBLK + 127) / 128);

    for (int l = 0; l < NLAY; l++) {
        // A = h@Wm1[l], B = h@Wm2[l] in one launch
        k_gemm<<<gridAB, 256>>>(s_h, Wm1 + (size_t)l * HID * EDGEF,
                                Wm2 + (size_t)l * HID * EDGEF, s_A, s_B,
                                NBLK, EDGEF, HID, 0, 4);
        k_zero4<<<8192, 256>>>(s_agg, (NBLK * EDGEF) / 4);
        k_edge_tc<<<2048, 256>>>(s_ssrc, s_sdst, s_Wc + (size_t)l * 64 * 256,
                                 s_A, s_B, s_rbf, s_agg);
        k_gemm<<<gridUpd, 256>>>(s_agg, Wupd + (size_t)l * EDGEF * HID, nullptr,
                                 s_h, nullptr, NBLK, HID, EDGEF, 1, 2);
    }

    // block_repr = l2norm(h @ W_out)
    k_gemm<<<gridUpd, 256>>>(s_h, W_out, nullptr, s_A, nullptr,
                             NBLK, HID, HID, 0, 2);
    k_rownorm_scatter<<<(NBLK * 32 + 255) / 256, 256>>>(s_A, batch_id,
                                                        out_block, s_gacc);
    k_graphnorm<<<(NG * 32 + 255) / 256, 256>>>(s_gacc, out_graph);
}

// round 5
// speedup vs baseline: 3.7064x; 1.8065x over previous
#include <cuda_runtime.h>
#include <cuda_bf16.h>
#include <math.h>

#define NATM 200000
#define NBLK 50000
#define NE   450000
#define NG   64
#define HID  128
#define RAD  64
#define EDGEF 256
#define NLAY 3
#define TABN 4096          // table entries per layer, spacing 1/256 over [0,16)
#define TABSCALE 256.0f

// ---- scratch layout (single __device__ buffer, floats) ----
static const size_t OFF_H     = 0;          // [NBLK*128]
static const size_t OFF_ZC    = 6400000;    // [NBLK*4] z0,z1,z2,cnt
static const size_t OFF_A     = 6600000;    // [NBLK*256]
static const size_t OFF_B     = 19400000;   // [NBLK*256]
static const size_t OFF_AGG   = 32200000;   // [NBLK*256]
static const size_t OFF_TAB   = 45000000;   // [3*4096*256]
static const size_t OFF_WC    = 48145728;   // [3*64*256]
static const size_t OFF_DE    = 48194880;   // [NE]
static const size_t OFF_GACC  = 48644880;   // [64*128]
static const size_t OFF_START = 48653072;   // int[NBLK+1]
static const size_t OFF_CNT   = 48703088;   // int[NBLK] (becomes end offsets)
static const size_t OFF_TOPS  = 48753104;   // int[128]
static const size_t OFF_SSRC  = 48753232;   // int[NE]
static const size_t OFF_SDST  = 49203232;   // int[NE]
static const size_t SCR_TOTAL = 49653248;

__device__ __align__(16) float g_scratch[SCR_TOTAL];

#define NTOPS 98   // ceil(NBLK/512)

__device__ __forceinline__ float silu_f(float x) {
    return x / (1.0f + __expf(-x));
}

__device__ __forceinline__ unsigned cvt_tf32(float f) {
    unsigned u;
    asm("cvt.rna.tf32.f32 %0, %1;" : "=r"(u) : "f"(f));
    return u;
}

__device__ __forceinline__ void mma_tf32(float* c, const unsigned* a,
                                         const unsigned* b) {
    asm volatile(
        "mma.sync.aligned.m16n8k8.row.col.f32.tf32.tf32.f32 "
        "{%0,%1,%2,%3}, {%4,%5,%6,%7}, {%8,%9}, {%0,%1,%2,%3};"
        : "+f"(c[0]), "+f"(c[1]), "+f"(c[2]), "+f"(c[3])
        : "r"(a[0]), "r"(a[1]), "r"(a[2]), "r"(a[3]), "r"(b[0]), "r"(b[1]));
}

__device__ __forceinline__ void red4(float* p, float4 v) {
    asm volatile("red.global.add.v4.f32 [%0], {%1,%2,%3,%4};"
                 :: "l"(p), "f"(v.x), "f"(v.y), "f"(v.z), "f"(v.w)
                 : "memory");
}

// ---------------------------------------------------------------------------
__global__ void k_zero4(float* __restrict__ p, int n4) {
    float4 z = make_float4(0.f, 0.f, 0.f, 0.f);
    for (int i = blockIdx.x * blockDim.x + threadIdx.x; i < n4;
         i += gridDim.x * blockDim.x) {
        ((float4*)p)[i] = z;
    }
}

// ---------------------------------------------------------------------------
// segment boundaries of sorted block_id
// ---------------------------------------------------------------------------
__global__ void k_bounds(const int* __restrict__ bid, int* __restrict__ start) {
    int a = blockIdx.x * blockDim.x + threadIdx.x;
    if (a > NATM) return;
    if (a == 0) {
        int c = bid[0];
        for (int b = 0; b <= c; b++) start[b] = 0;
    } else if (a == NATM) {
        int p = bid[NATM - 1];
        for (int b = p + 1; b <= NBLK; b++) start[b] = NATM;
    } else {
        int p = bid[a - 1], c = bid[a];
        for (int b = p + 1; b <= c; b++) start[b] = a;
    }
}

// ---------------------------------------------------------------------------
// segment-mean pooling: one warp per block
// ---------------------------------------------------------------------------
__global__ void k_pool(const float* __restrict__ H, const float* __restrict__ Z,
                       const int* __restrict__ start, float* __restrict__ h,
                       float* __restrict__ zc, float* __restrict__ outHb) {
    int gt = blockIdx.x * blockDim.x + threadIdx.x;
    int b = gt >> 5;
    int lane = gt & 31;
    if (b >= NBLK) return;
    int lo = start[b], hi = start[b + 1];
    float4 hs = make_float4(0.f, 0.f, 0.f, 0.f);
    for (int a = lo; a < hi; a++) {
        float4 v = *(const float4*)&H[(size_t)a * HID + lane * 4];
        hs.x += v.x; hs.y += v.y; hs.z += v.z; hs.w += v.w;
    }
    float zx = 0.f, zy = 0.f, zz = 0.f;
    for (int a = lo + lane; a < hi; a += 32) {
        zx += Z[a * 3 + 0]; zy += Z[a * 3 + 1]; zz += Z[a * 3 + 2];
    }
#pragma unroll
    for (int o = 16; o > 0; o >>= 1) {
        zx += __shfl_xor_sync(0xffffffffu, zx, o);
        zy += __shfl_xor_sync(0xffffffffu, zy, o);
        zz += __shfl_xor_sync(0xffffffffu, zz, o);
    }
    float cnt = (float)(hi - lo);
    float inv = 1.0f / fmaxf(cnt, 1.0f);
    hs.x *= inv; hs.y *= inv; hs.z *= inv; hs.w *= inv;
    *(float4*)&h[(size_t)b * HID + lane * 4] = hs;
    *(float4*)&outHb[(size_t)b * HID + lane * 4] = hs;
    if (lane == 0) {
        zc[b * 4 + 0] = zx * inv;
        zc[b * 4 + 1] = zy * inv;
        zc[b * 4 + 2] = zz * inv;
        zc[b * 4 + 3] = cnt;
    }
}

// ---------------------------------------------------------------------------
// counting sort of edges by dst
// ---------------------------------------------------------------------------
__global__ void k_hist(const int* __restrict__ edges, int* __restrict__ cnt) {
    int e = blockIdx.x * blockDim.x + threadIdx.x;
    if (e < NE) atomicAdd(&cnt[edges[NE + e]], 1);
}

__global__ void k_scan1(const int* __restrict__ cnt, int* __restrict__ offs,
                        int* __restrict__ tops) {
    __shared__ int sh[512];
    int i = blockIdx.x * 512 + threadIdx.x;
    int v = (i < NBLK) ? cnt[i] : 0;
    sh[threadIdx.x] = v;
    __syncthreads();
#pragma unroll
    for (int off = 1; off < 512; off <<= 1) {
        int t = 0;
        if (threadIdx.x >= off) t = sh[threadIdx.x - off];
        __syncthreads();
        if (threadIdx.x >= off) sh[threadIdx.x] += t;
        __syncthreads();
    }
    if (i < NBLK) offs[i] = sh[threadIdx.x] - v;
    if (threadIdx.x == 511) tops[blockIdx.x] = sh[511];
}

__global__ void k_scan2(int* __restrict__ tops) {
    __shared__ int sh[128];
    int v = (threadIdx.x < NTOPS) ? tops[threadIdx.x] : 0;
    sh[threadIdx.x] = v;
    __syncthreads();
#pragma unroll
    for (int off = 1; off < 128; off <<= 1) {
        int t = 0;
        if (threadIdx.x >= off) t = sh[threadIdx.x - off];
        __syncthreads();
        if (threadIdx.x >= off) sh[threadIdx.x] += t;
        __syncthreads();
    }
    if (threadIdx.x < NTOPS) tops[threadIdx.x] = sh[threadIdx.x] - v;
}

__global__ void k_scan3(int* __restrict__ offs, const int* __restrict__ tops) {
    int i = blockIdx.x * 512 + threadIdx.x;
    if (i < NBLK) offs[i] += tops[blockIdx.x];
}

__global__ void k_scat(const int* __restrict__ edges, int* __restrict__ offs,
                       int* __restrict__ ssrc, int* __restrict__ sdst) {
    int e = blockIdx.x * blockDim.x + threadIdx.x;
    if (e >= NE) return;
    int d = edges[NE + e];
    int pos = atomicAdd(&offs[d], 1);
    ssrc[pos] = edges[e];
    sdst[pos] = d;
}
// after k_scat, offs[d] holds the END offset of dst-segment d.

// ---------------------------------------------------------------------------
// per-edge distance (sorted order)
// ---------------------------------------------------------------------------
__global__ void k_dist(const int* __restrict__ ssrc, const int* __restrict__ sdst,
                       const float* __restrict__ zc, float* __restrict__ de) {
    int e = blockIdx.x * blockDim.x + threadIdx.x;
    if (e >= NE) return;
    int s = ssrc[e];
    int t = sdst[e];
    float dx = zc[s * 4 + 0] - zc[t * 4 + 0];
    float dy = zc[s * 4 + 1] - zc[t * 4 + 1];
    float dz = zc[s * 4 + 2] - zc[t * 4 + 2];
    de[e] = sqrtf(dx * dx + dy * dy + dz * dz + 1e-12f);
}

// ---------------------------------------------------------------------------
// build lookup table T[l][g][j] = rbf(g/256) @ Wc[l]
// grid (TABN, 3), 256 threads
// ---------------------------------------------------------------------------
__global__ void k_table(const float* __restrict__ Wc, float* __restrict__ T) {
    __shared__ float rb[64];
    int g = blockIdx.x, l = blockIdx.y;
    int tid = threadIdx.x;
    if (tid < 64) {
        float dd = (float)g * (1.0f / TABSCALE) - (6.0f / 63.0f) * (float)tid;
        rb[tid] = __expf(-10.0f * dd * dd);
    }
    __syncthreads();
    const float* W = Wc + (size_t)l * 64 * 256;
    float acc = 0.f;
#pragma unroll 16
    for (int k = 0; k < 64; k++) acc += rb[k] * W[k * 256 + tid];
    T[((size_t)l * TABN + g) * 256 + tid] = acc;
}

// ---------------------------------------------------------------------------
// tf32 tensor GEMM, double-buffered: C[M,N] = A[M,K] @ B[K,N]
// BM=128 BN=64 BK=32, 256 threads. block.x >= ntiles0 -> (B1,C1).
// epi==1: C += silu(acc). Requires K%32==0, N%64==0.
// ---------------------------------------------------------------------------
__global__ void __launch_bounds__(256)
k_gemm(const float* __restrict__ A, const float* __restrict__ B0,
       const float* __restrict__ B1, float* __restrict__ C0,
       float* __restrict__ C1, int M, int N, int K, int epi, int ntiles0) {
    __shared__ unsigned As[128 * 36];
    __shared__ unsigned Bs[32 * 68];
    int tid = threadIdx.x;
    int warp = tid >> 5, lane = tid & 31;
    int gid = lane >> 2, tig = lane & 3;
    int wm = (warp & 3) * 32, wn = (warp >> 2) * 32;
    int rowBase = blockIdx.y * 128;
    int bx = blockIdx.x;
    const float* B = B0;
    float* C = C0;
    if (bx >= ntiles0) { B = B1; C = C1; bx -= ntiles0; }
    int colBase = bx * 64;

    int ar = tid >> 3, ac = (tid & 7) * 4;
    int br = tid >> 4, bc = (tid & 15) * 4;

    float4 av[4], bv[2];
#pragma unroll
    for (int i = 0; i < 4; i++) {
        int r = rowBase + ar + i * 32;
        av[i] = (r < M) ? *(const float4*)&A[(size_t)r * K + ac]
                        : make_float4(0.f, 0.f, 0.f, 0.f);
    }
#pragma unroll
    for (int i = 0; i < 2; i++)
        bv[i] = *(const float4*)&B[(size_t)(br + i * 16) * N + colBase + bc];

    float acc[2][4][4];
#pragma unroll
    for (int mt = 0; mt < 2; mt++)
#pragma unroll
        for (int nn = 0; nn < 4; nn++)
#pragma unroll
            for (int q = 0; q < 4; q++) acc[mt][nn][q] = 0.f;

    for (int k0 = 0; k0 < K; k0 += 32) {
#pragma unroll
        for (int i = 0; i < 4; i++) {
            uint4 u;
            u.x = cvt_tf32(av[i].x); u.y = cvt_tf32(av[i].y);
            u.z = cvt_tf32(av[i].z); u.w = cvt_tf32(av[i].w);
            *(uint4*)&As[(ar + i * 32) * 36 + ac] = u;
        }
#pragma unroll
        for (int i = 0; i < 2; i++) {
            uint4 u;
            u.x = cvt_tf32(bv[i].x); u.y = cvt_tf32(bv[i].y);
            u.z = cvt_tf32(bv[i].z); u.w = cvt_tf32(bv[i].w);
            *(uint4*)&Bs[(br + i * 16) * 68 + bc] = u;
        }
        __syncthreads();
        if (k0 + 32 < K) {
#pragma unroll
            for (int i = 0; i < 4; i++) {
                int r = rowBase + ar + i * 32;
                av[i] = (r < M)
                    ? *(const float4*)&A[(size_t)r * K + k0 + 32 + ac]
                    : make_float4(0.f, 0.f, 0.f, 0.f);
            }
#pragma unroll
            for (int i = 0; i < 2; i++)
                bv[i] = *(const float4*)
                    &B[(size_t)(k0 + 32 + br + i * 16) * N + colBase + bc];
        }
#pragma unroll
        for (int kk = 0; kk < 4; kk++) {
            unsigned a[2][4], b[4][2];
#pragma unroll
            for (int mt = 0; mt < 2; mt++) {
                int r = wm + mt * 16 + gid;
                a[mt][0] = As[r * 36 + kk * 8 + tig];
                a[mt][1] = As[(r + 8) * 36 + kk * 8 + tig];
                a[mt][2] = As[r * 36 + kk * 8 + tig + 4];
                a[mt][3] = As[(r + 8) * 36 + kk * 8 + tig + 4];
            }
#pragma unroll
            for (int nn = 0; nn < 4; nn++) {
                b[nn][0] = Bs[(kk * 8 + tig) * 68 + wn + nn * 8 + gid];
                b[nn][1] = Bs[(kk * 8 + tig + 4) * 68 + wn + nn * 8 + gid];
            }
#pragma unroll
            for (int mt = 0; mt < 2; mt++)
#pragma unroll
                for (int nn = 0; nn < 4; nn++)
                    mma_tf32(acc[mt][nn], a[mt], b[nn]);
        }
        __syncthreads();
    }

#pragma unroll
    for (int mt = 0; mt < 2; mt++) {
#pragma unroll
        for (int nn = 0; nn < 4; nn++) {
            int r0 = rowBase + wm + mt * 16 + gid;
            int r1 = r0 + 8;
            int c = colBase + wn + nn * 8 + 2 * tig;
            if (r0 < M) {
                size_t idx = (size_t)r0 * N + c;
                if (epi == 1) {
                    C[idx]     += silu_f(acc[mt][nn][0]);
                    C[idx + 1] += silu_f(acc[mt][nn][1]);
                } else {
                    C[idx]     = acc[mt][nn][0];
                    C[idx + 1] = acc[mt][nn][1];
                }
            }
            if (r1 < M) {
                size_t idx = (size_t)r1 * N + c;
                if (epi == 1) {
                    C[idx]     += silu_f(acc[mt][nn][2]);
                    C[idx + 1] += silu_f(acc[mt][nn][3]);
                } else {
                    C[idx]     = acc[mt][nn][2];
                    C[idx + 1] = acc[mt][nn][3];
                }
            }
        }
    }
}

// ---------------------------------------------------------------------------
// edge+aggregate kernel: one warp per dst block.
// agg[d] = sum_{e in seg(d)} silu(A[src_e] + B[d] + lerp(T, de[e]))
// Plain stores (no atomics, no pre-zero). Table rows hot in L2.
// ---------------------------------------------------------------------------
__global__ void __launch_bounds__(256)
k_edge_lut(const int* __restrict__ ssrc, const int* __restrict__ eend,
           const float* __restrict__ Tl, const float* __restrict__ de,
           const float* __restrict__ Ag, const float* __restrict__ Bg,
           float* __restrict__ agg) {
    int gt = blockIdx.x * blockDim.x + threadIdx.x;
    int d = gt >> 5;
    int lane = gt & 31;
    if (d >= NBLK) return;
    int lo = (d > 0) ? eend[d - 1] : 0;
    int hi = eend[d];
    int c0 = lane * 4;
    int c1 = 128 + lane * 4;

    float4 acc0 = make_float4(0.f, 0.f, 0.f, 0.f);
    float4 acc1 = make_float4(0.f, 0.f, 0.f, 0.f);

    if (lo < hi) {
        float4 b0 = *(const float4*)&Bg[(size_t)d * 256 + c0];
        float4 b1 = *(const float4*)&Bg[(size_t)d * 256 + c1];
        for (int e = lo; e < hi; e++) {
            int s = ssrc[e];
            float t = fminf(de[e] * TABSCALE, (float)(TABN - 2) + 0.999f);
            int it = (int)t;
            float f = t - (float)it;
            const float* r0 = Tl + (size_t)it * 256;
            const float* r1 = r0 + 256;
            float4 a0 = *(const float4*)&Ag[(size_t)s * 256 + c0];
            float4 a1 = *(const float4*)&Ag[(size_t)s * 256 + c1];
            float4 u00 = *(const float4*)&r0[c0];
            float4 u01 = *(const float4*)&r0[c1];
            float4 u10 = *(const float4*)&r1[c0];
            float4 u11 = *(const float4*)&r1[c1];
            float4 m0, m1;
            m0.x = silu_f(a0.x + b0.x + u00.x + f * (u10.x - u00.x));
            m0.y = silu_f(a0.y + b0.y + u00.y + f * (u10.y - u00.y));
            m0.z = silu_f(a0.z + b0.z + u00.z + f * (u10.z - u00.z));
            m0.w = silu_f(a0.w + b0.w + u00.w + f * (u10.w - u00.w));
            m1.x = silu_f(a1.x + b1.x + u01.x + f * (u11.x - u01.x));
            m1.y = silu_f(a1.y + b1.y + u01.y + f * (u11.y - u01.y));
            m1.z = silu_f(a1.z + b1.z + u01.z + f * (u11.z - u01.z));
            m1.w = silu_f(a1.w + b1.w + u01.w + f * (u11.w - u01.w));
            acc0.x += m0.x; acc0.y += m0.y; acc0.z += m0.z; acc0.w += m0.w;
            acc1.x += m1.x; acc1.y += m1.y; acc1.z += m1.z; acc1.w += m1.w;
        }
    }
    *(float4*)&agg[(size_t)d * 256 + c0] = acc0;
    *(float4*)&agg[(size_t)d * 256 + c1] = acc1;
}

// ---------------------------------------------------------------------------
__global__ void k_rownorm_scatter(const float* __restrict__ tmp,
                                  const int* __restrict__ batch_id,
                                  float* __restrict__ out_block,
                                  float* __restrict__ gacc) {
    int gt = blockIdx.x * blockDim.x + threadIdx.x;
    int r = gt >> 5;
    int lane = gt & 31;
    if (r >= NBLK) return;
    float4 v = *(const float4*)&tmp[(size_t)r * HID + lane * 4];
    float ss = v.x * v.x + v.y * v.y + v.z * v.z + v.w * v.w;
#pragma unroll
    for (int o = 16; o > 0; o >>= 1) ss += __shfl_xor_sync(0xffffffffu, ss, o);
    float inv = 1.0f / fmaxf(sqrtf(ss), 1e-12f);
    int g = batch_id[r];
    float4 nv = make_float4(v.x * inv, v.y * inv, v.z * inv, v.w * inv);
    *(float4*)&out_block[(size_t)r * HID + lane * 4] = nv;
    red4(&gacc[g * HID + lane * 4], nv);
}

__global__ void k_graphnorm(const float* __restrict__ gacc,
                            float* __restrict__ out_graph) {
    int gt = blockIdx.x * blockDim.x + threadIdx.x;
    int r = gt >> 5;
    int lane = gt & 31;
    if (r >= NG) return;
    float4 v = *(const float4*)&gacc[r * HID + lane * 4];
    float ss = v.x * v.x + v.y * v.y + v.z * v.z + v.w * v.w;
#pragma unroll
    for (int o = 16; o > 0; o >>= 1) ss += __shfl_xor_sync(0xffffffffu, ss, o);
    float inv = 1.0f / fmaxf(sqrtf(ss), 1e-12f);
    float4 nv = make_float4(v.x * inv, v.y * inv, v.z * inv, v.w * inv);
    *(float4*)&out_graph[r * HID + lane * 4] = nv;
}

// ---------------------------------------------------------------------------
extern "C" void kernel_launch(void* const* d_in, const int* in_sizes, int n_in,
                              void* d_out, int out_size) {
    const float* H      = (const float*)d_in[0];
    const float* Z      = (const float*)d_in[1];
    const float* W_rbf  = (const float*)d_in[2];
    const float* Wm1    = (const float*)d_in[3];
    const float* Wm2    = (const float*)d_in[4];
    const float* We     = (const float*)d_in[5];
    const float* Wupd   = (const float*)d_in[6];
    const float* W_out  = (const float*)d_in[7];
    const int*   block_id = (const int*)d_in[8];
    const int*   batch_id = (const int*)d_in[9];
    const int*   edges    = (const int*)d_in[10];

    float* out = (float*)d_out;
    float* out_Hb    = out;
    float* out_block = out + (size_t)NBLK * HID;
    float* out_graph = out + 2 * (size_t)NBLK * HID;

    void* scrv = nullptr;
    cudaGetSymbolAddress(&scrv, g_scratch);
    float* scr  = (float*)scrv;
    float* s_h    = scr + OFF_H;
    float* s_zc   = scr + OFF_ZC;
    float* s_A    = scr + OFF_A;
    float* s_B    = scr + OFF_B;
    float* s_agg  = scr + OFF_AGG;
    float* s_tab  = scr + OFF_TAB;
    float* s_Wc   = scr + OFF_WC;
    float* s_de   = scr + OFF_DE;
    float* s_gacc = scr + OFF_GACC;
    int*   s_start = (int*)(scr + OFF_START);
    int*   s_cnt   = (int*)(scr + OFF_CNT);
    int*   s_tops  = (int*)(scr + OFF_TOPS);
    int*   s_ssrc  = (int*)(scr + OFF_SSRC);
    int*   s_sdst  = (int*)(scr + OFF_SDST);

    // Wc[l] = W_rbf @ We[l], then build interpolation table
    for (int l = 0; l < NLAY; l++) {
        k_gemm<<<dim3(4, 1), 256>>>(W_rbf, We + (size_t)l * 256 * 256, nullptr,
                                    s_Wc + (size_t)l * 64 * 256, nullptr,
                                    64, 256, 256, 0, 4);
    }
    k_table<<<dim3(TABN, NLAY), 256>>>(s_Wc, s_tab);

    // pooling via sorted segments
    k_bounds<<<(NATM + 256) / 256, 256>>>(block_id, s_start);
    k_pool<<<(NBLK * 32 + 255) / 256, 256>>>(H, Z, s_start, s_h, s_zc, out_Hb);

    // counting sort of edges by dst (s_cnt ends as END offsets)
    k_zero4<<<32, 256>>>((float*)s_cnt, 50016 / 4);
    k_hist<<<(NE + 255) / 256, 256>>>(edges, s_cnt);
    k_scan1<<<NTOPS, 512>>>(s_cnt, s_cnt, s_tops);
    k_scan2<<<1, 128>>>(s_tops);
    k_scan3<<<NTOPS, 512>>>(s_cnt, s_tops);
    k_scat<<<(NE + 255) / 256, 256>>>(edges, s_cnt, s_ssrc, s_sdst);

    // per-edge distances
    k_dist<<<(NE + 255) / 256, 256>>>(s_ssrc, s_sdst, s_zc, s_de);

    // zero graph accumulator
    k_zero4<<<8, 256>>>(s_gacc, (NG * HID) / 4);

    dim3 gridAB(8, (NBLK + 127) / 128);
    dim3 gridUpd(2, (NBLK + 127) / 128);

    for (int l = 0; l < NLAY; l++) {
        // A = h@Wm1[l], B = h@Wm2[l] in one launch
        k_gemm<<<gridAB, 256>>>(s_h, Wm1 + (size_t)l * HID * EDGEF,
                                Wm2 + (size_t)l * HID * EDGEF, s_A, s_B,
                                NBLK, EDGEF, HID, 0, 4);
        // fused edge messages + per-dst aggregation (plain stores)
        k_edge_lut<<<(NBLK * 32 + 255) / 256, 256>>>(
            s_ssrc, s_cnt, s_tab + (size_t)l * TABN * 256, s_de, s_A, s_B,
            s_agg);
        // h = h + silu(agg @ Wupd[l])
        k_gemm<<<gridUpd, 256>>>(s_agg, Wupd + (size_t)l * EDGEF * HID, nullptr,
                                 s_h, nullptr, NBLK, HID, EDGEF, 1, 2);
    }

    // block_repr = l2norm(h @ W_out)
    k_gemm<<<gridUpd, 256>>>(s_h, W_out, nullptr, s_A, nullptr,
                             NBLK, HID, HID, 0, 2);
    k_rownorm_scatter<<<(NBLK * 32 + 255) / 256, 256>>>(s_A, batch_id,
                                                        out_block, s_gacc);
    k_graphnorm<<<(NG * 32 + 255) / 256, 256>>>(s_gacc, out_graph);
}